// round 7
// baseline (speedup 1.0000x reference)
#include <cuda_runtime.h>
#include <cuda_bf16.h>
#include <math.h>
#include <math_constants.h>
#include <cstdint>

#define T_   2048
#define DM_  4096
#define H_   16
#define HD_  256
#define RD_  64
#define DFF_ 16384

// ---------------- scratch (device globals) ----------------
__device__ __nv_bfloat16 g_wqkvT_hi[(size_t)3*DM_*DM_];
__device__ __nv_bfloat16 g_wqkvT_lo[(size_t)3*DM_*DM_];
__device__ __nv_bfloat16 g_woutT_hi[(size_t)DM_*DM_];
__device__ __nv_bfloat16 g_woutT_lo[(size_t)DM_*DM_];
__device__ __nv_bfloat16 g_wfciT_hi[(size_t)DFF_*DM_];
__device__ __nv_bfloat16 g_wfciT_lo[(size_t)DFF_*DM_];
__device__ __nv_bfloat16 g_wfcoT_hi[(size_t)DM_*DFF_];
__device__ __nv_bfloat16 g_wfcoT_lo[(size_t)DM_*DFF_];
__device__ __nv_bfloat16 g_ln_hi[(size_t)T_*DM_];
__device__ __nv_bfloat16 g_ln_lo[(size_t)T_*DM_];
__device__ __nv_bfloat16 g_act_hi[(size_t)T_*DFF_];
__device__ __nv_bfloat16 g_act_lo[(size_t)T_*DFF_];
__device__ __nv_bfloat16 g_ctx_hi[(size_t)T_*DM_];
__device__ __nv_bfloat16 g_ctx_lo[(size_t)T_*DM_];
__device__ float g_qkv[(size_t)T_*3*DM_];

// ---------------- PTX helpers (baseline features only) --------
__device__ __forceinline__ uint32_t smem_u32(const void* p) {
    uint32_t a;
    asm("{ .reg .u64 t; cvta.to.shared.u64 t, %1; cvt.u32.u64 %0, t; }" : "=r"(a) : "l"(p));
    return a;
}
__device__ __forceinline__ void cp_async16(uint32_t d, const void* g) {
    asm volatile("cp.async.cg.shared.global [%0], [%1], 16;" :: "r"(d), "l"(g));
}
#define CP_COMMIT()  asm volatile("cp.async.commit_group;" ::: "memory")
#define CP_WAIT1()   asm volatile("cp.async.wait_group 1;" ::: "memory")

__device__ __forceinline__ void ldsm4(uint32_t* r, uint32_t addr) {
    asm volatile("ldmatrix.sync.aligned.m8n8.x4.shared.b16 {%0,%1,%2,%3}, [%4];"
                 : "=r"(r[0]), "=r"(r[1]), "=r"(r[2]), "=r"(r[3]) : "r"(addr));
}
__device__ __forceinline__ void mma16816(float* c, const uint32_t* a,
                                         uint32_t b0, uint32_t b1) {
    asm volatile("mma.sync.aligned.m16n8k16.row.col.f32.bf16.bf16.f32 "
                 "{%0,%1,%2,%3}, {%4,%5,%6,%7}, {%8,%9}, {%0,%1,%2,%3};"
                 : "+f"(c[0]), "+f"(c[1]), "+f"(c[2]), "+f"(c[3])
                 : "r"(a[0]), "r"(a[1]), "r"(a[2]), "r"(a[3]), "r"(b0), "r"(b1));
}

__device__ __forceinline__ void split_store(float v, __nv_bfloat16* ph, __nv_bfloat16* pl) {
    __nv_bfloat16 h = __float2bfloat16(v);
    *ph = h;
    *pl = __float2bfloat16(v - __bfloat162float(h));
}

// ---------------- weight transpose + bf16 split ----------------
__global__ void convT_kernel(const float* __restrict__ W,
                             __nv_bfloat16* __restrict__ hi,
                             __nv_bfloat16* __restrict__ lo,
                             int Krows, int Ncols) {
    __shared__ float tile[32][33];
    int n0 = blockIdx.x * 32, k0 = blockIdx.y * 32;
    int tx = threadIdx.x, ty = threadIdx.y;
#pragma unroll
    for (int i = 0; i < 4; i++)
        tile[ty + 8 * i][tx] = W[(size_t)(k0 + ty + 8 * i) * Ncols + n0 + tx];
    __syncthreads();
#pragma unroll
    for (int i = 0; i < 4; i++) {
        int r = ty + 8 * i;
        float v = tile[tx][r];
        size_t o = (size_t)(n0 + r) * Krows + k0 + tx;
        __nv_bfloat16 h = __float2bfloat16(v);
        hi[o] = h;
        lo[o] = __float2bfloat16(v - __bfloat162float(h));
    }
}

// ---------------- LayerNorm -> bf16 hi/lo ----------------
__global__ void ln_kernel(const float* __restrict__ x,
                          const float* __restrict__ gamma,
                          const float* __restrict__ beta,
                          __nv_bfloat16* __restrict__ ohi,
                          __nv_bfloat16* __restrict__ olo) {
    int row = blockIdx.x;
    const float4* xr = (const float4*)(x + (size_t)row * DM_);
    float4 v[4];
    float sum = 0.f, sq = 0.f;
#pragma unroll
    for (int i = 0; i < 4; i++) {
        v[i] = xr[threadIdx.x + 256 * i];
        sum += v[i].x + v[i].y + v[i].z + v[i].w;
        sq  += v[i].x * v[i].x + v[i].y * v[i].y + v[i].z * v[i].z + v[i].w * v[i].w;
    }
#pragma unroll
    for (int o = 16; o; o >>= 1) {
        sum += __shfl_xor_sync(0xffffffffu, sum, o);
        sq  += __shfl_xor_sync(0xffffffffu, sq,  o);
    }
    __shared__ float ssum[8], ssq[8];
    int warp = threadIdx.x >> 5, lane = threadIdx.x & 31;
    if (lane == 0) { ssum[warp] = sum; ssq[warp] = sq; }
    __syncthreads();
    sum = 0.f; sq = 0.f;
#pragma unroll
    for (int i = 0; i < 8; i++) { sum += ssum[i]; sq += ssq[i]; }
    float mu  = sum * (1.0f / DM_);
    float var = sq * (1.0f / DM_) - mu * mu;
    float inv = rsqrtf(var + 1e-5f);
    const float4* g4 = (const float4*)gamma;
    const float4* b4 = (const float4*)beta;
#pragma unroll
    for (int i = 0; i < 4; i++) {
        int idx = threadIdx.x + 256 * i;
        float4 g = g4[idx], b = b4[idx];
        size_t base = (size_t)row * DM_ + idx * 4;
        split_store((v[i].x - mu) * inv * g.x + b.x, ohi + base + 0, olo + base + 0);
        split_store((v[i].y - mu) * inv * g.y + b.y, ohi + base + 1, olo + base + 1);
        split_store((v[i].z - mu) * inv * g.z + b.z, ohi + base + 2, olo + base + 2);
        split_store((v[i].w - mu) * inv * g.w + b.w, ohi + base + 3, olo + base + 3);
    }
}

// ---------------- RoPE (GPT-J interleaved) ----------------
__global__ void rope_kernel(float* __restrict__ qkv, const int* __restrict__ positions) {
    int idx = blockIdx.x * blockDim.x + threadIdx.x;
    int i     = idx & 31;
    int which = (idx >> 5) & 1;
    int h     = (idx >> 6) & 15;
    int t     = idx >> 10;
    float inv = (float)pow(10000.0, -(double)i / 32.0);
    float ang = (float)positions[t] * inv;
    float s, c;
    sincosf(ang, &s, &c);
    float* p = qkv + (size_t)t * (3 * DM_) + (size_t)which * DM_ + h * HD_ + 2 * i;
    float x1 = p[0], x2 = p[1];
    p[0] = x1 * c - x2 * s;
    p[1] = x2 * c + x1 * s;
}

__device__ __forceinline__ float gelu_tanh(float x) {
    float x3 = x * x * x;
    float t  = tanhf(0.7978845608028654f * (x + 0.044715f * x3));
    return 0.5f * x * (1.0f + t);
}

// ---------------- mma.sync split-bf16 GEMM ----------------
// CTA tile 128x256, 512 threads (16 warps, warp tile 64x32), KC=32,
// 2-stage cp.async double buffer. Rows padded to 40 bf16 (80B).
// EPI: 0 store fp32; 1 gelu(v+bias)->Ohi/Olo; 2 v+bias+res->C; 3 C += v
#define KC 32
#define ROWB 80                                // padded row bytes
#define ARR_A (128 * ROWB)                     // 10240
#define ARR_B (256 * ROWB)                     // 20480
#define ALO_OFF ARR_A                          // 10240
#define BHI_OFF (2 * ARR_A)                    // 20480
#define BLO_OFF (2 * ARR_A + ARR_B)            // 40960
#define STAGE_BYTES (2 * ARR_A + 2 * ARR_B)    // 61440
#define GEMM_SMEM (2 * STAGE_BYTES)            // 122880

template <int EPI>
__global__ void __launch_bounds__(512, 1)
mma_gemm(const __nv_bfloat16* __restrict__ Ahi, const __nv_bfloat16* __restrict__ Alo,
         const __nv_bfloat16* __restrict__ Bhi, const __nv_bfloat16* __restrict__ Blo,
         float* __restrict__ C,
         __nv_bfloat16* __restrict__ Ohi, __nv_bfloat16* __restrict__ Olo,
         const float* __restrict__ bias, const float* __restrict__ res,
         int M, int N, int K) {
    extern __shared__ char smem[];
    const uint32_t sb0 = smem_u32(smem);
    int tid = threadIdx.x;
    int lane = tid & 31, wid = tid >> 5;
    int wm = wid >> 3, wn = wid & 7;           // 2 x 8 warp grid

    // supertile rasterization for L2 reuse
    int nbn = N / 256, nbm = M / 128;
    const int SWT = 4;
    int per = SWT * nbm;
    int ggrp = blockIdx.x / per, rem = blockIdx.x - ggrp * per;
    int bn0 = ggrp * SWT;
    int w = nbn - bn0; if (w > SWT) w = SWT;
    int bn = bn0 + rem % w;
    int bm = rem / w;

    float acc[4][4][4];
#pragma unroll
    for (int i = 0; i < 4; i++)
#pragma unroll
        for (int j = 0; j < 4; j++)
#pragma unroll
            for (int q = 0; q < 4; q++) acc[i][j][q] = 0.f;

    auto load_stage = [&](int s, int k0) {
        uint32_t sb = sb0 + s * STAGE_BYTES;
        // A hi/lo: 512 chunks each, one per thread
        {
            int row = tid >> 2, c = tid & 3;
            size_t go = (size_t)(bm * 128 + row) * K + k0 + c * 8;
            uint32_t d = row * ROWB + c * 16;
            cp_async16(sb + d,           Ahi + go);
            cp_async16(sb + ALO_OFF + d, Alo + go);
        }
        // B hi/lo: 1024 chunks each, two per thread
#pragma unroll
        for (int j = 0; j < 2; j++) {
            int ch = tid + 512 * j;
            int row = ch >> 2, c = ch & 3;
            size_t go = (size_t)(bn * 256 + row) * K + k0 + c * 8;
            uint32_t d = row * ROWB + c * 16;
            cp_async16(sb + BHI_OFF + d, Bhi + go);
            cp_async16(sb + BLO_OFF + d, Blo + go);
        }
    };

    load_stage(0, 0); CP_COMMIT();
    load_stage(1, KC); CP_COMMIT();

    uint32_t aBase = sb0 + (wm * 64 + (lane & 15)) * ROWB + ((lane >> 4) * 8) * 2;
    uint32_t bBase = sb0 + BHI_OFF + (wn * 32 + (lane & 15)) * ROWB + ((lane >> 4) * 8) * 2;

    int nk = K / KC;
    for (int kc = 0; kc < nk; kc++) {
        CP_WAIT1();
        __syncthreads();
        uint32_t so = (kc & 1) * STAGE_BYTES;
#pragma unroll
        for (int ks = 0; ks < 2; ks++) {
            uint32_t bh[8], bl[8];
            ldsm4(bh,     bBase + so + ks * 32);
            ldsm4(bh + 4, bBase + so + 16 * ROWB + ks * 32);
            ldsm4(bl,     bBase + so + (BLO_OFF - BHI_OFF) + ks * 32);
            ldsm4(bl + 4, bBase + so + (BLO_OFF - BHI_OFF) + 16 * ROWB + ks * 32);
#pragma unroll
            for (int i = 0; i < 4; i++) {
                uint32_t ah[4], al[4];
                ldsm4(ah, aBase + so + i * 16 * ROWB + ks * 32);
                ldsm4(al, aBase + so + ALO_OFF + i * 16 * ROWB + ks * 32);
#pragma unroll
                for (int j = 0; j < 4; j++) {
                    int j2 = j >> 1, ss = j & 1;
                    uint32_t b0h = bh[j2 * 4 + ss], b1h = bh[j2 * 4 + ss + 2];
                    uint32_t b0l = bl[j2 * 4 + ss], b1l = bl[j2 * 4 + ss + 2];
                    mma16816(acc[i][j], ah, b0h, b1h);
                    mma16816(acc[i][j], ah, b0l, b1l);
                    mma16816(acc[i][j], al, b0h, b1h);
                }
            }
        }
        __syncthreads();
        if (kc + 2 < nk) load_stage(kc & 1, (kc + 2) * KC);
        CP_COMMIT();
    }

    // epilogue
    int gq = lane >> 2, cc = lane & 3;
#pragma unroll
    for (int i = 0; i < 4; i++) {
#pragma unroll
        for (int j = 0; j < 4; j++) {
            int row = bm * 128 + wm * 64 + i * 16 + gq;
            int col = bn * 256 + wn * 32 + j * 8 + 2 * cc;
            float* a4 = acc[i][j];
#pragma unroll
            for (int half = 0; half < 2; half++) {
                int r = row + 8 * half;
                float v0 = a4[2 * half], v1 = a4[2 * half + 1];
                size_t base = (size_t)r * N + col;
                if (EPI == 0) {
                    *(float2*)(C + base) = make_float2(v0, v1);
                } else if (EPI == 1) {
                    float g0 = gelu_tanh(v0 + bias[col]);
                    float g1 = gelu_tanh(v1 + bias[col + 1]);
                    split_store(g0, Ohi + base, Olo + base);
                    split_store(g1, Ohi + base + 1, Olo + base + 1);
                } else if (EPI == 2) {
                    float2 rr = *(const float2*)(res + base);
                    *(float2*)(C + base) = make_float2(v0 + bias[col] + rr.x,
                                                       v1 + bias[col + 1] + rr.y);
                } else {
                    float2 cur = *(float2*)(C + base);
                    *(float2*)(C + base) = make_float2(cur.x + v0, cur.y + v1);
                }
            }
        }
    }
}

// ---------------- causal flash attention (fp32), ctx -> bf16 hi/lo ----------------
#define BQ 32
#define BK 32
__global__ void __launch_bounds__(256)
attn_kernel(const float* __restrict__ qkv,
            __nv_bfloat16* __restrict__ chi, __nv_bfloat16* __restrict__ clo) {
    extern __shared__ float smemf[];
    float* Ks = smemf;
    float* Vs = smemf + BK * HD_;
    int h  = blockIdx.y;
    int qb = blockIdx.x;
    int tid = threadIdx.x;
    int q = tid >> 3;
    int c = tid & 7;
    int tq = qb * BQ + q;

    const float* qrow = qkv + (size_t)tq * (3 * DM_) + h * HD_;
    float qreg[32];
#pragma unroll
    for (int j = 0; j < 8; j++) {
        float4 v = *(const float4*)(qrow + c * 4 + 32 * j);
        qreg[4 * j + 0] = v.x; qreg[4 * j + 1] = v.y;
        qreg[4 * j + 2] = v.z; qreg[4 * j + 3] = v.w;
    }
    float acc[32];
#pragma unroll
    for (int j = 0; j < 32; j++) acc[j] = 0.f;
    float m = -CUDART_INF_F, l = 0.f;
    const float scale = 0.0625f;

    int ntiles = qb + 1;
    for (int kt = 0; kt < ntiles; ++kt) {
        __syncthreads();
        {
            int r  = tid >> 3;
            int cc = tid & 7;
            const float* krow = qkv + (size_t)(kt * BK + r) * (3 * DM_) + DM_ + h * HD_;
            const float* vrow = krow + DM_;
#pragma unroll
            for (int j = 0; j < 8; j++) {
                *(float4*)(Ks + r * HD_ + cc * 4 + 32 * j) = *(const float4*)(krow + cc * 4 + 32 * j);
                *(float4*)(Vs + r * HD_ + cc * 4 + 32 * j) = *(const float4*)(vrow + cc * 4 + 32 * j);
            }
        }
        __syncthreads();

        float s[32];
        float mloc = -CUDART_INF_F;
#pragma unroll 4
        for (int kk = 0; kk < BK; ++kk) {
            const float* kr = Ks + kk * HD_;
            float part = 0.f;
#pragma unroll
            for (int j = 0; j < 8; j++) {
                float4 v = *(const float4*)(kr + c * 4 + 32 * j);
                part += qreg[4 * j] * v.x + qreg[4 * j + 1] * v.y
                      + qreg[4 * j + 2] * v.z + qreg[4 * j + 3] * v.w;
            }
            part += __shfl_xor_sync(0xffffffffu, part, 1);
            part += __shfl_xor_sync(0xffffffffu, part, 2);
            part += __shfl_xor_sync(0xffffffffu, part, 4);
            part *= scale;
            int tk = kt * BK + kk;
            if (tk > tq) part = -CUDART_INF_F;
            s[kk] = part;
            mloc = fmaxf(mloc, part);
        }
        float mnew  = fmaxf(m, mloc);
        float alpha = __expf(m - mnew);
        l *= alpha;
#pragma unroll
        for (int j = 0; j < 32; j++) acc[j] *= alpha;
#pragma unroll 4
        for (int kk = 0; kk < BK; ++kk) {
            float p = __expf(s[kk] - mnew);
            l += p;
            const float* vr = Vs + kk * HD_;
#pragma unroll
            for (int j = 0; j < 8; j++) {
                float4 v = *(const float4*)(vr + c * 4 + 32 * j);
                acc[4 * j + 0] += p * v.x;
                acc[4 * j + 1] += p * v.y;
                acc[4 * j + 2] += p * v.z;
                acc[4 * j + 3] += p * v.w;
            }
        }
        m = mnew;
    }

    float invl = 1.0f / l;
    size_t obase = (size_t)tq * DM_ + h * HD_;
#pragma unroll
    for (int j = 0; j < 8; j++) {
#pragma unroll
        for (int ii = 0; ii < 4; ii++) {
            float v = acc[4 * j + ii] * invl;
            size_t o = obase + c * 4 + 32 * j + ii;
            split_store(v, chi + o, clo + o);
        }
    }
}

// ---------------- launch ----------------
extern "C" void kernel_launch(void* const* d_in, const int* in_sizes, int n_in,
                              void* d_out, int out_size) {
    const int*   positions = (const int*)  d_in[0];
    const float* hidden    = (const float*)d_in[1];
    const float* ln_g      = (const float*)d_in[2];
    const float* ln_b      = (const float*)d_in[3];
    const float* w_qkv     = (const float*)d_in[4];
    const float* w_out     = (const float*)d_in[5];
    const float* w_fc_in   = (const float*)d_in[6];
    const float* b_fc_in   = (const float*)d_in[7];
    const float* w_fc_out  = (const float*)d_in[8];
    const float* b_fc_out  = (const float*)d_in[9];
    float* out = (float*)d_out;

    __nv_bfloat16 *wqh, *wql, *woh, *wol, *wih, *wil, *wfh, *wfl;
    __nv_bfloat16 *lnh, *lnl, *ach, *acl, *cxh, *cxl;
    float *p_qkv;
    cudaGetSymbolAddress((void**)&wqh, g_wqkvT_hi);  cudaGetSymbolAddress((void**)&wql, g_wqkvT_lo);
    cudaGetSymbolAddress((void**)&woh, g_woutT_hi);  cudaGetSymbolAddress((void**)&wol, g_woutT_lo);
    cudaGetSymbolAddress((void**)&wih, g_wfciT_hi);  cudaGetSymbolAddress((void**)&wil, g_wfciT_lo);
    cudaGetSymbolAddress((void**)&wfh, g_wfcoT_hi);  cudaGetSymbolAddress((void**)&wfl, g_wfcoT_lo);
    cudaGetSymbolAddress((void**)&lnh, g_ln_hi);     cudaGetSymbolAddress((void**)&lnl, g_ln_lo);
    cudaGetSymbolAddress((void**)&ach, g_act_hi);    cudaGetSymbolAddress((void**)&acl, g_act_lo);
    cudaGetSymbolAddress((void**)&cxh, g_ctx_hi);    cudaGetSymbolAddress((void**)&cxl, g_ctx_lo);
    cudaGetSymbolAddress((void**)&p_qkv, g_qkv);

    cudaFuncSetAttribute(mma_gemm<0>, cudaFuncAttributeMaxDynamicSharedMemorySize, GEMM_SMEM);
    cudaFuncSetAttribute(mma_gemm<1>, cudaFuncAttributeMaxDynamicSharedMemorySize, GEMM_SMEM);
    cudaFuncSetAttribute(mma_gemm<2>, cudaFuncAttributeMaxDynamicSharedMemorySize, GEMM_SMEM);
    cudaFuncSetAttribute(mma_gemm<3>, cudaFuncAttributeMaxDynamicSharedMemorySize, GEMM_SMEM);
    cudaFuncSetAttribute(attn_kernel, cudaFuncAttributeMaxDynamicSharedMemorySize,
                         2 * BK * HD_ * (int)sizeof(float));

    dim3 cb(32, 8);
    convT_kernel<<<dim3(3 * DM_ / 32, DM_ / 32), cb>>>(w_qkv,   wqh, wql, DM_,  3 * DM_);
    convT_kernel<<<dim3(DM_ / 32,     DM_ / 32), cb>>>(w_out,   woh, wol, DM_,  DM_);
    convT_kernel<<<dim3(DFF_ / 32,    DM_ / 32), cb>>>(w_fc_in, wih, wil, DM_,  DFF_);
    convT_kernel<<<dim3(DM_ / 32,    DFF_ / 32), cb>>>(w_fc_out,wfh, wfl, DFF_, DM_);

    ln_kernel<<<T_, 256>>>(hidden, ln_g, ln_b, lnh, lnl);

    // QKV GEMM -> fp32 qkv
    mma_gemm<0><<<(T_ / 128) * (3 * DM_ / 256), 512, GEMM_SMEM>>>(
        lnh, lnl, wqh, wql, p_qkv, nullptr, nullptr, nullptr, nullptr,
        T_, 3 * DM_, DM_);

    rope_kernel<<<(T_ * H_ * 64) / 256, 256>>>(p_qkv, positions);

    attn_kernel<<<dim3(T_ / BQ, H_), 256, 2 * BK * HD_ * sizeof(float)>>>(p_qkv, cxh, cxl);

    // fc_in + gelu -> act hi/lo
    mma_gemm<1><<<(T_ / 128) * (DFF_ / 256), 512, GEMM_SMEM>>>(
        lnh, lnl, wih, wil, nullptr, ach, acl, b_fc_in, nullptr,
        T_, DFF_, DM_);

    // fc_out + bias + residual -> out
    mma_gemm<2><<<(T_ / 128) * (DM_ / 256), 512, GEMM_SMEM>>>(
        ach, acl, wfh, wfl, out, nullptr, nullptr, b_fc_out, hidden,
        T_, DM_, DFF_);

    // attention out-proj, accumulate into out
    mma_gemm<3><<<(T_ / 128) * (DM_ / 256), 512, GEMM_SMEM>>>(
        cxh, cxl, woh, wol, out, nullptr, nullptr, nullptr, nullptr,
        T_, DM_, DM_);
}

// round 9
// speedup vs baseline: 1.5998x; 1.5998x over previous
#include <cuda_runtime.h>
#include <cuda_bf16.h>
#include <math.h>
#include <math_constants.h>
#include <cstdint>

#define T_   2048
#define DM_  4096
#define H_   16
#define HD_  256
#define RD_  64
#define DFF_ 16384

// ---------------- scratch (device globals) ----------------
__device__ __nv_bfloat16 g_wqkvT_hi[(size_t)3*DM_*DM_];
__device__ __nv_bfloat16 g_wqkvT_lo[(size_t)3*DM_*DM_];
__device__ __nv_bfloat16 g_woutT_hi[(size_t)DM_*DM_];
__device__ __nv_bfloat16 g_woutT_lo[(size_t)DM_*DM_];
__device__ __nv_bfloat16 g_wfciT_hi[(size_t)DFF_*DM_];
__device__ __nv_bfloat16 g_wfciT_lo[(size_t)DFF_*DM_];
__device__ __nv_bfloat16 g_wfcoT_hi[(size_t)DM_*DFF_];
__device__ __nv_bfloat16 g_wfcoT_lo[(size_t)DM_*DFF_];
__device__ __nv_bfloat16 g_ln_hi[(size_t)T_*DM_];
__device__ __nv_bfloat16 g_ln_lo[(size_t)T_*DM_];
__device__ __nv_bfloat16 g_act_hi[(size_t)T_*DFF_];
__device__ __nv_bfloat16 g_act_lo[(size_t)T_*DFF_];
__device__ __nv_bfloat16 g_ctx_hi[(size_t)T_*DM_];
__device__ __nv_bfloat16 g_ctx_lo[(size_t)T_*DM_];
__device__ float g_qkv[(size_t)T_*3*DM_];

// ---------------- PTX helpers (baseline features only) --------
__device__ __forceinline__ uint32_t smem_u32(const void* p) {
    uint32_t a;
    asm("{ .reg .u64 t; cvta.to.shared.u64 t, %1; cvt.u32.u64 %0, t; }" : "=r"(a) : "l"(p));
    return a;
}
__device__ __forceinline__ void cp_async16(uint32_t d, const void* g) {
    asm volatile("cp.async.cg.shared.global [%0], [%1], 16;" :: "r"(d), "l"(g));
}
#define CP_COMMIT()  asm volatile("cp.async.commit_group;" ::: "memory")
#define CP_WAIT1()   asm volatile("cp.async.wait_group 1;" ::: "memory")

__device__ __forceinline__ void ldsm4(uint32_t* r, uint32_t addr) {
    asm volatile("ldmatrix.sync.aligned.m8n8.x4.shared.b16 {%0,%1,%2,%3}, [%4];"
                 : "=r"(r[0]), "=r"(r[1]), "=r"(r[2]), "=r"(r[3]) : "r"(addr));
}
__device__ __forceinline__ void mma16816(float* c, const uint32_t* a,
                                         uint32_t b0, uint32_t b1) {
    asm volatile("mma.sync.aligned.m16n8k16.row.col.f32.bf16.bf16.f32 "
                 "{%0,%1,%2,%3}, {%4,%5,%6,%7}, {%8,%9}, {%0,%1,%2,%3};"
                 : "+f"(c[0]), "+f"(c[1]), "+f"(c[2]), "+f"(c[3])
                 : "r"(a[0]), "r"(a[1]), "r"(a[2]), "r"(a[3]), "r"(b0), "r"(b1));
}

__device__ __forceinline__ void split_store(float v, __nv_bfloat16* ph, __nv_bfloat16* pl) {
    __nv_bfloat16 h = __float2bfloat16(v);
    *ph = h;
    *pl = __float2bfloat16(v - __bfloat162float(h));
}

// ---------------- weight transpose + bf16 split ----------------
__global__ void convT_kernel(const float* __restrict__ W,
                             __nv_bfloat16* __restrict__ hi,
                             __nv_bfloat16* __restrict__ lo,
                             int Krows, int Ncols) {
    __shared__ float tile[32][33];
    int n0 = blockIdx.x * 32, k0 = blockIdx.y * 32;
    int tx = threadIdx.x, ty = threadIdx.y;
#pragma unroll
    for (int i = 0; i < 4; i++)
        tile[ty + 8 * i][tx] = W[(size_t)(k0 + ty + 8 * i) * Ncols + n0 + tx];
    __syncthreads();
#pragma unroll
    for (int i = 0; i < 4; i++) {
        int r = ty + 8 * i;
        float v = tile[tx][r];
        size_t o = (size_t)(n0 + r) * Krows + k0 + tx;
        __nv_bfloat16 h = __float2bfloat16(v);
        hi[o] = h;
        lo[o] = __float2bfloat16(v - __bfloat162float(h));
    }
}

// ---------------- LayerNorm -> bf16 hi/lo ----------------
__global__ void ln_kernel(const float* __restrict__ x,
                          const float* __restrict__ gamma,
                          const float* __restrict__ beta,
                          __nv_bfloat16* __restrict__ ohi,
                          __nv_bfloat16* __restrict__ olo) {
    int row = blockIdx.x;
    const float4* xr = (const float4*)(x + (size_t)row * DM_);
    float4 v[4];
    float sum = 0.f, sq = 0.f;
#pragma unroll
    for (int i = 0; i < 4; i++) {
        v[i] = xr[threadIdx.x + 256 * i];
        sum += v[i].x + v[i].y + v[i].z + v[i].w;
        sq  += v[i].x * v[i].x + v[i].y * v[i].y + v[i].z * v[i].z + v[i].w * v[i].w;
    }
#pragma unroll
    for (int o = 16; o; o >>= 1) {
        sum += __shfl_xor_sync(0xffffffffu, sum, o);
        sq  += __shfl_xor_sync(0xffffffffu, sq,  o);
    }
    __shared__ float ssum[8], ssq[8];
    int warp = threadIdx.x >> 5, lane = threadIdx.x & 31;
    if (lane == 0) { ssum[warp] = sum; ssq[warp] = sq; }
    __syncthreads();
    sum = 0.f; sq = 0.f;
#pragma unroll
    for (int i = 0; i < 8; i++) { sum += ssum[i]; sq += ssq[i]; }
    float mu  = sum * (1.0f / DM_);
    float var = sq * (1.0f / DM_) - mu * mu;
    float inv = rsqrtf(var + 1e-5f);
    const float4* g4 = (const float4*)gamma;
    const float4* b4 = (const float4*)beta;
#pragma unroll
    for (int i = 0; i < 4; i++) {
        int idx = threadIdx.x + 256 * i;
        float4 g = g4[idx], b = b4[idx];
        size_t base = (size_t)row * DM_ + idx * 4;
        split_store((v[i].x - mu) * inv * g.x + b.x, ohi + base + 0, olo + base + 0);
        split_store((v[i].y - mu) * inv * g.y + b.y, ohi + base + 1, olo + base + 1);
        split_store((v[i].z - mu) * inv * g.z + b.z, ohi + base + 2, olo + base + 2);
        split_store((v[i].w - mu) * inv * g.w + b.w, ohi + base + 3, olo + base + 3);
    }
}

// ---------------- RoPE (GPT-J interleaved) ----------------
__global__ void rope_kernel(float* __restrict__ qkv, const int* __restrict__ positions) {
    int idx = blockIdx.x * blockDim.x + threadIdx.x;
    int i     = idx & 31;
    int which = (idx >> 5) & 1;
    int h     = (idx >> 6) & 15;
    int t     = idx >> 10;
    float inv = (float)pow(10000.0, -(double)i / 32.0);
    float ang = (float)positions[t] * inv;
    float s, c;
    sincosf(ang, &s, &c);
    float* p = qkv + (size_t)t * (3 * DM_) + (size_t)which * DM_ + h * HD_ + 2 * i;
    float x1 = p[0], x2 = p[1];
    p[0] = x1 * c - x2 * s;
    p[1] = x2 * c + x1 * s;
}

__device__ __forceinline__ float gelu_tanh(float x) {
    float x3 = x * x * x;
    float t  = tanhf(0.7978845608028654f * (x + 0.044715f * x3));
    return 0.5f * x * (1.0f + t);
}

// ---------------- mma.sync split-bf16 GEMM ----------------
// CTA 128x128, 256 threads, warp tile 64x32 (2x4 warp grid), KC=32.
// 2-stage cp.async pipeline, 2 CTAs/SM (smem 80KB/CTA, regs capped at 128).
// EPI: 0 store fp32; 1 gelu(v+bias)->Ohi/Olo; 2 v+bias+res->C; 3 C += v
#define KC 32
#define ROWP 40                               // padded row, bf16 elems
#define ARR_BYTES (128 * ROWP * 2)            // 10240
#define STAGE_BYTES (4 * ARR_BYTES)           // 40960: Ahi,Alo,Bhi,Blo
#define NSTAGE 2
#define GEMM_SMEM (NSTAGE * STAGE_BYTES)      // 81920

template <int EPI>
__global__ void __launch_bounds__(256, 2)
mma_gemm(const __nv_bfloat16* __restrict__ Ahi, const __nv_bfloat16* __restrict__ Alo,
         const __nv_bfloat16* __restrict__ Bhi, const __nv_bfloat16* __restrict__ Blo,
         float* __restrict__ C,
         __nv_bfloat16* __restrict__ Ohi, __nv_bfloat16* __restrict__ Olo,
         const float* __restrict__ bias, const float* __restrict__ res,
         int M, int N, int K) {
    extern __shared__ char smem[];
    const uint32_t sb0 = smem_u32(smem);
    int tid = threadIdx.x;
    int lane = tid & 31, wid = tid >> 5;
    int wm = wid >> 2, wn = wid & 3;

    // supertile rasterization (groups of 8 N-blocks) for L2 reuse
    int nbn = N / 128, nbm = M / 128;
    const int SWT = 8;
    int per = SWT * nbm;
    int ggrp = blockIdx.x / per, rem = blockIdx.x - ggrp * per;
    int bn0 = ggrp * SWT;
    int w = nbn - bn0; if (w > SWT) w = SWT;
    int bn = bn0 + rem % w;
    int bm = rem / w;

    float acc[4][4][4];
#pragma unroll
    for (int i = 0; i < 4; i++)
#pragma unroll
        for (int j = 0; j < 4; j++)
#pragma unroll
            for (int q = 0; q < 4; q++) acc[i][j][q] = 0.f;

    auto load_stage = [&](int s, int k0) {
        uint32_t sb = sb0 + s * STAGE_BYTES;
#pragma unroll
        for (int arr = 0; arr < 4; arr++) {
            const __nv_bfloat16* g = (arr == 0) ? Ahi : (arr == 1) ? Alo
                                   : (arr == 2) ? Bhi : Blo;
            size_t rb = (arr < 2) ? (size_t)bm * 128 : (size_t)bn * 128;
#pragma unroll
            for (int j = 0; j < 2; j++) {
                int i = tid + 256 * j;          // 0..511
                int row = i >> 2, c = i & 3;    // 4 x 16B chunks per 64B row
                cp_async16(sb + arr * ARR_BYTES + row * (ROWP * 2) + c * 16,
                           g + (rb + row) * (size_t)K + k0 + c * 8);
            }
        }
    };

    load_stage(0, 0); CP_COMMIT();
    load_stage(1, KC); CP_COMMIT();

    uint32_t aBase = sb0 + (wm * 64 + (lane & 15)) * (ROWP * 2) + ((lane >> 4) * 8) * 2;
    uint32_t bBase = sb0 + 2 * ARR_BYTES + (wn * 32 + (lane & 15)) * (ROWP * 2) + ((lane >> 4) * 8) * 2;

    int nk = K / KC;
    for (int kc = 0; kc < nk; kc++) {
        CP_WAIT1();
        __syncthreads();
        uint32_t so = (kc & 1) * STAGE_BYTES;
#pragma unroll
        for (int ks = 0; ks < 2; ks++) {
            uint32_t bh[8], bl[8];
            ldsm4(bh,     bBase + so + ks * 32);
            ldsm4(bh + 4, bBase + so + 16 * (ROWP * 2) + ks * 32);
            ldsm4(bl,     bBase + so + ARR_BYTES + ks * 32);
            ldsm4(bl + 4, bBase + so + ARR_BYTES + 16 * (ROWP * 2) + ks * 32);
#pragma unroll
            for (int i = 0; i < 4; i++) {
                uint32_t ah[4], al[4];
                ldsm4(ah, aBase + so + i * 16 * (ROWP * 2) + ks * 32);
                ldsm4(al, aBase + so + ARR_BYTES + i * 16 * (ROWP * 2) + ks * 32);
#pragma unroll
                for (int j = 0; j < 4; j++) {
                    int j2 = j >> 1, ss = j & 1;
                    uint32_t b0h = bh[j2 * 4 + ss], b1h = bh[j2 * 4 + ss + 2];
                    uint32_t b0l = bl[j2 * 4 + ss], b1l = bl[j2 * 4 + ss + 2];
                    mma16816(acc[i][j], ah, b0h, b1h);
                    mma16816(acc[i][j], ah, b0l, b1l);
                    mma16816(acc[i][j], al, b0h, b1h);
                }
            }
        }
        __syncthreads();
        if (kc + 2 < nk) load_stage(kc & 1, (kc + 2) * KC);
        CP_COMMIT();
    }

    // epilogue: acc thread mapping: g=lane>>2, cc=lane&3
    int gq = lane >> 2, cc = lane & 3;
#pragma unroll
    for (int i = 0; i < 4; i++) {
#pragma unroll
        for (int j = 0; j < 4; j++) {
            int row = bm * 128 + wm * 64 + i * 16 + gq;
            int col = bn * 128 + wn * 32 + j * 8 + 2 * cc;
            float* a4 = acc[i][j];
#pragma unroll
            for (int half = 0; half < 2; half++) {
                int r = row + 8 * half;
                float v0 = a4[2 * half], v1 = a4[2 * half + 1];
                size_t base = (size_t)r * N + col;
                if (EPI == 0) {
                    *(float2*)(C + base) = make_float2(v0, v1);
                } else if (EPI == 1) {
                    float g0 = gelu_tanh(v0 + bias[col]);
                    float g1 = gelu_tanh(v1 + bias[col + 1]);
                    split_store(g0, Ohi + base, Olo + base);
                    split_store(g1, Ohi + base + 1, Olo + base + 1);
                } else if (EPI == 2) {
                    float2 rr = *(const float2*)(res + base);
                    *(float2*)(C + base) = make_float2(v0 + bias[col] + rr.x,
                                                       v1 + bias[col + 1] + rr.y);
                } else {
                    float2 cur = *(float2*)(C + base);
                    *(float2*)(C + base) = make_float2(cur.x + v0, cur.y + v1);
                }
            }
        }
    }
}

// ---------------- causal flash attention (fp32), ctx -> bf16 hi/lo ----------------
#define BQ 32
#define BK 32
__global__ void __launch_bounds__(256)
attn_kernel(const float* __restrict__ qkv,
            __nv_bfloat16* __restrict__ chi, __nv_bfloat16* __restrict__ clo) {
    extern __shared__ float smemf[];
    float* Ks = smemf;
    float* Vs = smemf + BK * HD_;
    int h  = blockIdx.y;
    int qb = blockIdx.x;
    int tid = threadIdx.x;
    int q = tid >> 3;
    int c = tid & 7;
    int tq = qb * BQ + q;

    const float* qrow = qkv + (size_t)tq * (3 * DM_) + h * HD_;
    float qreg[32];
#pragma unroll
    for (int j = 0; j < 8; j++) {
        float4 v = *(const float4*)(qrow + c * 4 + 32 * j);
        qreg[4 * j + 0] = v.x; qreg[4 * j + 1] = v.y;
        qreg[4 * j + 2] = v.z; qreg[4 * j + 3] = v.w;
    }
    float acc[32];
#pragma unroll
    for (int j = 0; j < 32; j++) acc[j] = 0.f;
    float m = -CUDART_INF_F, l = 0.f;
    const float scale = 0.0625f;

    int ntiles = qb + 1;
    for (int kt = 0; kt < ntiles; ++kt) {
        __syncthreads();
        {
            int r  = tid >> 3;
            int cc = tid & 7;
            const float* krow = qkv + (size_t)(kt * BK + r) * (3 * DM_) + DM_ + h * HD_;
            const float* vrow = krow + DM_;
#pragma unroll
            for (int j = 0; j < 8; j++) {
                *(float4*)(Ks + r * HD_ + cc * 4 + 32 * j) = *(const float4*)(krow + cc * 4 + 32 * j);
                *(float4*)(Vs + r * HD_ + cc * 4 + 32 * j) = *(const float4*)(vrow + cc * 4 + 32 * j);
            }
        }
        __syncthreads();

        float s[32];
        float mloc = -CUDART_INF_F;
#pragma unroll 4
        for (int kk = 0; kk < BK; ++kk) {
            const float* kr = Ks + kk * HD_;
            float part = 0.f;
#pragma unroll
            for (int j = 0; j < 8; j++) {
                float4 v = *(const float4*)(kr + c * 4 + 32 * j);
                part += qreg[4 * j] * v.x + qreg[4 * j + 1] * v.y
                      + qreg[4 * j + 2] * v.z + qreg[4 * j + 3] * v.w;
            }
            part += __shfl_xor_sync(0xffffffffu, part, 1);
            part += __shfl_xor_sync(0xffffffffu, part, 2);
            part += __shfl_xor_sync(0xffffffffu, part, 4);
            part *= scale;
            int tk = kt * BK + kk;
            if (tk > tq) part = -CUDART_INF_F;
            s[kk] = part;
            mloc = fmaxf(mloc, part);
        }
        float mnew  = fmaxf(m, mloc);
        float alpha = __expf(m - mnew);
        l *= alpha;
#pragma unroll
        for (int j = 0; j < 32; j++) acc[j] *= alpha;
#pragma unroll 4
        for (int kk = 0; kk < BK; ++kk) {
            float p = __expf(s[kk] - mnew);
            l += p;
            const float* vr = Vs + kk * HD_;
#pragma unroll
            for (int j = 0; j < 8; j++) {
                float4 v = *(const float4*)(vr + c * 4 + 32 * j);
                acc[4 * j + 0] += p * v.x;
                acc[4 * j + 1] += p * v.y;
                acc[4 * j + 2] += p * v.z;
                acc[4 * j + 3] += p * v.w;
            }
        }
        m = mnew;
    }

    float invl = 1.0f / l;
    size_t obase = (size_t)tq * DM_ + h * HD_;
#pragma unroll
    for (int j = 0; j < 8; j++) {
#pragma unroll
        for (int ii = 0; ii < 4; ii++) {
            float v = acc[4 * j + ii] * invl;
            size_t o = obase + c * 4 + 32 * j + ii;
            split_store(v, chi + o, clo + o);
        }
    }
}

// ---------------- launch ----------------
extern "C" void kernel_launch(void* const* d_in, const int* in_sizes, int n_in,
                              void* d_out, int out_size) {
    const int*   positions = (const int*)  d_in[0];
    const float* hidden    = (const float*)d_in[1];
    const float* ln_g      = (const float*)d_in[2];
    const float* ln_b      = (const float*)d_in[3];
    const float* w_qkv     = (const float*)d_in[4];
    const float* w_out     = (const float*)d_in[5];
    const float* w_fc_in   = (const float*)d_in[6];
    const float* b_fc_in   = (const float*)d_in[7];
    const float* w_fc_out  = (const float*)d_in[8];
    const float* b_fc_out  = (const float*)d_in[9];
    float* out = (float*)d_out;

    __nv_bfloat16 *wqh, *wql, *woh, *wol, *wih, *wil, *wfh, *wfl;
    __nv_bfloat16 *lnh, *lnl, *ach, *acl, *cxh, *cxl;
    float *p_qkv;
    cudaGetSymbolAddress((void**)&wqh, g_wqkvT_hi);  cudaGetSymbolAddress((void**)&wql, g_wqkvT_lo);
    cudaGetSymbolAddress((void**)&woh, g_woutT_hi);  cudaGetSymbolAddress((void**)&wol, g_woutT_lo);
    cudaGetSymbolAddress((void**)&wih, g_wfciT_hi);  cudaGetSymbolAddress((void**)&wil, g_wfciT_lo);
    cudaGetSymbolAddress((void**)&wfh, g_wfcoT_hi);  cudaGetSymbolAddress((void**)&wfl, g_wfcoT_lo);
    cudaGetSymbolAddress((void**)&lnh, g_ln_hi);     cudaGetSymbolAddress((void**)&lnl, g_ln_lo);
    cudaGetSymbolAddress((void**)&ach, g_act_hi);    cudaGetSymbolAddress((void**)&acl, g_act_lo);
    cudaGetSymbolAddress((void**)&cxh, g_ctx_hi);    cudaGetSymbolAddress((void**)&cxl, g_ctx_lo);
    cudaGetSymbolAddress((void**)&p_qkv, g_qkv);

    cudaFuncSetAttribute(mma_gemm<0>, cudaFuncAttributeMaxDynamicSharedMemorySize, GEMM_SMEM);
    cudaFuncSetAttribute(mma_gemm<1>, cudaFuncAttributeMaxDynamicSharedMemorySize, GEMM_SMEM);
    cudaFuncSetAttribute(mma_gemm<2>, cudaFuncAttributeMaxDynamicSharedMemorySize, GEMM_SMEM);
    cudaFuncSetAttribute(mma_gemm<3>, cudaFuncAttributeMaxDynamicSharedMemorySize, GEMM_SMEM);
    cudaFuncSetAttribute(attn_kernel, cudaFuncAttributeMaxDynamicSharedMemorySize,
                         2 * BK * HD_ * (int)sizeof(float));

    dim3 cb(32, 8);
    convT_kernel<<<dim3(3 * DM_ / 32, DM_ / 32), cb>>>(w_qkv,   wqh, wql, DM_,  3 * DM_);
    convT_kernel<<<dim3(DM_ / 32,     DM_ / 32), cb>>>(w_out,   woh, wol, DM_,  DM_);
    convT_kernel<<<dim3(DFF_ / 32,    DM_ / 32), cb>>>(w_fc_in, wih, wil, DM_,  DFF_);
    convT_kernel<<<dim3(DM_ / 32,    DFF_ / 32), cb>>>(w_fc_out,wfh, wfl, DFF_, DM_);

    ln_kernel<<<T_, 256>>>(hidden, ln_g, ln_b, lnh, lnl);

    // QKV GEMM -> fp32 qkv
    mma_gemm<0><<<(T_ / 128) * (3 * DM_ / 128), 256, GEMM_SMEM>>>(
        lnh, lnl, wqh, wql, p_qkv, nullptr, nullptr, nullptr, nullptr,
        T_, 3 * DM_, DM_);

    rope_kernel<<<(T_ * H_ * 64) / 256, 256>>>(p_qkv, positions);

    attn_kernel<<<dim3(T_ / BQ, H_), 256, 2 * BK * HD_ * sizeof(float)>>>(p_qkv, cxh, cxl);

    // fc_in + gelu -> act hi/lo
    mma_gemm<1><<<(T_ / 128) * (DFF_ / 128), 256, GEMM_SMEM>>>(
        lnh, lnl, wih, wil, nullptr, ach, acl, b_fc_in, nullptr,
        T_, DFF_, DM_);

    // fc_out + bias + residual -> out
    mma_gemm<2><<<(T_ / 128) * (DM_ / 128), 256, GEMM_SMEM>>>(
        ach, acl, wfh, wfl, out, nullptr, nullptr, b_fc_out, hidden,
        T_, DM_, DFF_);

    // attention out-proj, accumulate into out
    mma_gemm<3><<<(T_ / 128) * (DM_ / 128), 256, GEMM_SMEM>>>(
        cxh, cxl, woh, wol, out, nullptr, nullptr, nullptr, nullptr,
        T_, DM_, DM_);
}

// round 10
// speedup vs baseline: 1.8293x; 1.1435x over previous
#include <cuda_runtime.h>
#include <cuda_bf16.h>
#include <math.h>
#include <math_constants.h>
#include <cstdint>

#define T_   2048
#define DM_  4096
#define H_   16
#define HD_  256
#define RD_  64
#define DFF_ 16384

// ---------------- scratch (device globals) ----------------
__device__ __nv_bfloat16 g_wqkvT_hi[(size_t)3*DM_*DM_];
__device__ __nv_bfloat16 g_wqkvT_lo[(size_t)3*DM_*DM_];
__device__ __nv_bfloat16 g_woutT_hi[(size_t)DM_*DM_];
__device__ __nv_bfloat16 g_woutT_lo[(size_t)DM_*DM_];
__device__ __nv_bfloat16 g_wfciT_hi[(size_t)DFF_*DM_];
__device__ __nv_bfloat16 g_wfciT_lo[(size_t)DFF_*DM_];
__device__ __nv_bfloat16 g_wfcoT_hi[(size_t)DM_*DFF_];
__device__ __nv_bfloat16 g_wfcoT_lo[(size_t)DM_*DFF_];
__device__ __nv_bfloat16 g_ln_hi[(size_t)T_*DM_];
__device__ __nv_bfloat16 g_ln_lo[(size_t)T_*DM_];
__device__ __nv_bfloat16 g_act_hi[(size_t)T_*DFF_];
__device__ __nv_bfloat16 g_act_lo[(size_t)T_*DFF_];
__device__ __nv_bfloat16 g_ctx_hi[(size_t)T_*DM_];
__device__ __nv_bfloat16 g_ctx_lo[(size_t)T_*DM_];
__device__ float g_qkv[(size_t)T_*3*DM_];

// ---------------- PTX helpers (baseline features only) --------
__device__ __forceinline__ uint32_t smem_u32(const void* p) {
    uint32_t a;
    asm("{ .reg .u64 t; cvta.to.shared.u64 t, %1; cvt.u32.u64 %0, t; }" : "=r"(a) : "l"(p));
    return a;
}
__device__ __forceinline__ void cp_async16(uint32_t d, const void* g) {
    asm volatile("cp.async.cg.shared.global [%0], [%1], 16;" :: "r"(d), "l"(g));
}
#define CP_COMMIT()  asm volatile("cp.async.commit_group;" ::: "memory")
#define CP_WAIT1()   asm volatile("cp.async.wait_group 1;" ::: "memory")

__device__ __forceinline__ void ldsm4(uint32_t* r, uint32_t addr) {
    asm volatile("ldmatrix.sync.aligned.m8n8.x4.shared.b16 {%0,%1,%2,%3}, [%4];"
                 : "=r"(r[0]), "=r"(r[1]), "=r"(r[2]), "=r"(r[3]) : "r"(addr));
}
__device__ __forceinline__ void mma16816(float* c, const uint32_t* a,
                                         uint32_t b0, uint32_t b1) {
    asm volatile("mma.sync.aligned.m16n8k16.row.col.f32.bf16.bf16.f32 "
                 "{%0,%1,%2,%3}, {%4,%5,%6,%7}, {%8,%9}, {%0,%1,%2,%3};"
                 : "+f"(c[0]), "+f"(c[1]), "+f"(c[2]), "+f"(c[3])
                 : "r"(a[0]), "r"(a[1]), "r"(a[2]), "r"(a[3]), "r"(b0), "r"(b1));
}

__device__ __forceinline__ void split_store(float v, __nv_bfloat16* ph, __nv_bfloat16* pl) {
    __nv_bfloat16 h = __float2bfloat16(v);
    *ph = h;
    *pl = __float2bfloat16(v - __bfloat162float(h));
}

// ---------------- weight transpose + bf16 split ----------------
__global__ void convT_kernel(const float* __restrict__ W,
                             __nv_bfloat16* __restrict__ hi,
                             __nv_bfloat16* __restrict__ lo,
                             int Krows, int Ncols) {
    __shared__ float tile[32][33];
    int n0 = blockIdx.x * 32, k0 = blockIdx.y * 32;
    int tx = threadIdx.x, ty = threadIdx.y;
#pragma unroll
    for (int i = 0; i < 4; i++)
        tile[ty + 8 * i][tx] = W[(size_t)(k0 + ty + 8 * i) * Ncols + n0 + tx];
    __syncthreads();
#pragma unroll
    for (int i = 0; i < 4; i++) {
        int r = ty + 8 * i;
        float v = tile[tx][r];
        size_t o = (size_t)(n0 + r) * Krows + k0 + tx;
        __nv_bfloat16 h = __float2bfloat16(v);
        hi[o] = h;
        lo[o] = __float2bfloat16(v - __bfloat162float(h));
    }
}

// ---------------- LayerNorm -> bf16 hi/lo ----------------
__global__ void ln_kernel(const float* __restrict__ x,
                          const float* __restrict__ gamma,
                          const float* __restrict__ beta,
                          __nv_bfloat16* __restrict__ ohi,
                          __nv_bfloat16* __restrict__ olo) {
    int row = blockIdx.x;
    const float4* xr = (const float4*)(x + (size_t)row * DM_);
    float4 v[4];
    float sum = 0.f, sq = 0.f;
#pragma unroll
    for (int i = 0; i < 4; i++) {
        v[i] = xr[threadIdx.x + 256 * i];
        sum += v[i].x + v[i].y + v[i].z + v[i].w;
        sq  += v[i].x * v[i].x + v[i].y * v[i].y + v[i].z * v[i].z + v[i].w * v[i].w;
    }
#pragma unroll
    for (int o = 16; o; o >>= 1) {
        sum += __shfl_xor_sync(0xffffffffu, sum, o);
        sq  += __shfl_xor_sync(0xffffffffu, sq,  o);
    }
    __shared__ float ssum[8], ssq[8];
    int warp = threadIdx.x >> 5, lane = threadIdx.x & 31;
    if (lane == 0) { ssum[warp] = sum; ssq[warp] = sq; }
    __syncthreads();
    sum = 0.f; sq = 0.f;
#pragma unroll
    for (int i = 0; i < 8; i++) { sum += ssum[i]; sq += ssq[i]; }
    float mu  = sum * (1.0f / DM_);
    float var = sq * (1.0f / DM_) - mu * mu;
    float inv = rsqrtf(var + 1e-5f);
    const float4* g4 = (const float4*)gamma;
    const float4* b4 = (const float4*)beta;
#pragma unroll
    for (int i = 0; i < 4; i++) {
        int idx = threadIdx.x + 256 * i;
        float4 g = g4[idx], b = b4[idx];
        size_t base = (size_t)row * DM_ + idx * 4;
        split_store((v[i].x - mu) * inv * g.x + b.x, ohi + base + 0, olo + base + 0);
        split_store((v[i].y - mu) * inv * g.y + b.y, ohi + base + 1, olo + base + 1);
        split_store((v[i].z - mu) * inv * g.z + b.z, ohi + base + 2, olo + base + 2);
        split_store((v[i].w - mu) * inv * g.w + b.w, ohi + base + 3, olo + base + 3);
    }
}

// ---------------- RoPE (GPT-J interleaved) ----------------
__global__ void rope_kernel(float* __restrict__ qkv, const int* __restrict__ positions) {
    int idx = blockIdx.x * blockDim.x + threadIdx.x;
    int i     = idx & 31;
    int which = (idx >> 5) & 1;
    int h     = (idx >> 6) & 15;
    int t     = idx >> 10;
    float inv = (float)pow(10000.0, -(double)i / 32.0);
    float ang = (float)positions[t] * inv;
    float s, c;
    sincosf(ang, &s, &c);
    float* p = qkv + (size_t)t * (3 * DM_) + (size_t)which * DM_ + h * HD_ + 2 * i;
    float x1 = p[0], x2 = p[1];
    p[0] = x1 * c - x2 * s;
    p[1] = x2 * c + x1 * s;
}

__device__ __forceinline__ float gelu_tanh(float x) {
    float x3 = x * x * x;
    float t  = tanhf(0.7978845608028654f * (x + 0.044715f * x3));
    return 0.5f * x * (1.0f + t);
}

// ---------------- mma.sync split-bf16 GEMM ----------------
// CTA 128x128, 256 threads, warp tile 64x32 (2x4 warp grid), KC=32.
// 3-stage cp.async pipeline with XOR-swizzled 64B rows (no padding),
// single barrier per KC, 2 CTAs/SM.
// Swizzle: 16B chunk c of row r lives at r*64 + ((c ^ ((r>>1)&3))<<4).
// EPI: 0 store fp32; 1 gelu(v+bias)->Ohi/Olo; 2 v+bias+res->C; 3 C += v
#define KC 32
#define ARR_BYTES 8192                        // 128 rows x 64B
#define AHI_OFF 0
#define ALO_OFF 8192
#define BHI_OFF 16384
#define BLO_OFF 24576
#define STAGE_BYTES 32768
#define NSTAGE 3
#define GEMM_SMEM (NSTAGE * STAGE_BYTES)      // 98304

template <int EPI>
__global__ void __launch_bounds__(256, 2)
mma_gemm(const __nv_bfloat16* __restrict__ Ahi, const __nv_bfloat16* __restrict__ Alo,
         const __nv_bfloat16* __restrict__ Bhi, const __nv_bfloat16* __restrict__ Blo,
         float* __restrict__ C,
         __nv_bfloat16* __restrict__ Ohi, __nv_bfloat16* __restrict__ Olo,
         const float* __restrict__ bias, const float* __restrict__ res,
         int M, int N, int K) {
    extern __shared__ char smem[];
    const uint32_t sb0 = smem_u32(smem);
    int tid = threadIdx.x;
    int lane = tid & 31, wid = tid >> 5;
    int wm = wid >> 2, wn = wid & 3;

    // supertile rasterization (groups of 8 N-blocks) for L2 reuse
    int nbn = N / 128, nbm = M / 128;
    const int SWT = 8;
    int per = SWT * nbm;
    int ggrp = blockIdx.x / per, rem = blockIdx.x - ggrp * per;
    int bn0 = ggrp * SWT;
    int w = nbn - bn0; if (w > SWT) w = SWT;
    int bn = bn0 + rem % w;
    int bm = rem / w;

    float acc[4][4][4];
#pragma unroll
    for (int i = 0; i < 4; i++)
#pragma unroll
        for (int j = 0; j < 4; j++)
#pragma unroll
            for (int q = 0; q < 4; q++) acc[i][j][q] = 0.f;

    // cp.async loader: 512 chunks (16B) per array, 2 per thread per array
    auto load_stage = [&](int s, int k0) {
        uint32_t sb = sb0 + s * STAGE_BYTES;
#pragma unroll
        for (int j = 0; j < 2; j++) {
            int id  = tid + 256 * j;
            int row = id >> 2, c = id & 3;
            uint32_t d = row * 64 + ((c ^ ((row >> 1) & 3)) << 4);
            size_t goA = (size_t)(bm * 128 + row) * K + k0 + c * 8;
            size_t goB = (size_t)(bn * 128 + row) * K + k0 + c * 8;
            cp_async16(sb + AHI_OFF + d, Ahi + goA);
            cp_async16(sb + ALO_OFF + d, Alo + goA);
            cp_async16(sb + BHI_OFF + d, Bhi + goB);
            cp_async16(sb + BLO_OFF + d, Blo + goB);
        }
    };

    load_stage(0, 0); CP_COMMIT();
    load_stage(1, KC); CP_COMMIT();

    // per-lane ldmatrix row geometry
    int hi4 = lane >> 4;                 // chunk half-select (0/1)
    int rA[4], swA[4], rB0, rB1, swB0, swB1;
#pragma unroll
    for (int i = 0; i < 4; i++) {
        int r = wm * 64 + i * 16 + (lane & 15);
        rA[i] = r * 64;
        swA[i] = (r >> 1) & 3;
    }
    {
        int r0 = wn * 32 + (lane & 15);
        int r1 = r0 + 16;
        rB0 = r0 * 64; swB0 = (r0 >> 1) & 3;
        rB1 = r1 * 64; swB1 = (r1 >> 1) & 3;
    }

    int nk = K / KC;
    int st = 0, ld = 2;
    for (int kc = 0; kc < nk; kc++) {
        CP_WAIT1();
        __syncthreads();
        if (kc + 2 < nk) load_stage(ld, (kc + 2) * KC);
        CP_COMMIT();
        uint32_t base = sb0 + st * STAGE_BYTES;
#pragma unroll
        for (int ks = 0; ks < 2; ks++) {
            int c = ks * 2 + hi4;
            uint32_t bh[8], bl[8];
            ldsm4(bh,     base + BHI_OFF + rB0 + ((c ^ swB0) << 4));
            ldsm4(bh + 4, base + BHI_OFF + rB1 + ((c ^ swB1) << 4));
            ldsm4(bl,     base + BLO_OFF + rB0 + ((c ^ swB0) << 4));
            ldsm4(bl + 4, base + BLO_OFF + rB1 + ((c ^ swB1) << 4));
#pragma unroll
            for (int i = 0; i < 4; i++) {
                uint32_t ah[4], al[4];
                ldsm4(ah, base + AHI_OFF + rA[i] + ((c ^ swA[i]) << 4));
                ldsm4(al, base + ALO_OFF + rA[i] + ((c ^ swA[i]) << 4));
#pragma unroll
                for (int j = 0; j < 4; j++) {
                    int j2 = j >> 1, ss = j & 1;
                    uint32_t b0h = bh[j2 * 4 + ss], b1h = bh[j2 * 4 + ss + 2];
                    uint32_t b0l = bl[j2 * 4 + ss], b1l = bl[j2 * 4 + ss + 2];
                    mma16816(acc[i][j], ah, b0h, b1h);
                    mma16816(acc[i][j], ah, b0l, b1l);
                    mma16816(acc[i][j], al, b0h, b1h);
                }
            }
        }
        st = (st == 2) ? 0 : st + 1;
        ld = (ld == 2) ? 0 : ld + 1;
    }

    // epilogue: acc thread mapping: g=lane>>2, cc=lane&3
    int gq = lane >> 2, cc = lane & 3;
#pragma unroll
    for (int i = 0; i < 4; i++) {
#pragma unroll
        for (int j = 0; j < 4; j++) {
            int row = bm * 128 + wm * 64 + i * 16 + gq;
            int col = bn * 128 + wn * 32 + j * 8 + 2 * cc;
            float* a4 = acc[i][j];
#pragma unroll
            for (int half = 0; half < 2; half++) {
                int r = row + 8 * half;
                float v0 = a4[2 * half], v1 = a4[2 * half + 1];
                size_t base = (size_t)r * N + col;
                if (EPI == 0) {
                    *(float2*)(C + base) = make_float2(v0, v1);
                } else if (EPI == 1) {
                    float g0 = gelu_tanh(v0 + bias[col]);
                    float g1 = gelu_tanh(v1 + bias[col + 1]);
                    split_store(g0, Ohi + base, Olo + base);
                    split_store(g1, Ohi + base + 1, Olo + base + 1);
                } else if (EPI == 2) {
                    float2 rr = *(const float2*)(res + base);
                    *(float2*)(C + base) = make_float2(v0 + bias[col] + rr.x,
                                                       v1 + bias[col + 1] + rr.y);
                } else {
                    float2 cur = *(float2*)(C + base);
                    *(float2*)(C + base) = make_float2(cur.x + v0, cur.y + v1);
                }
            }
        }
    }
}

// ---------------- causal flash attention (fp32), ctx -> bf16 hi/lo ----------------
#define BQ 32
#define BK 32
__global__ void __launch_bounds__(256)
attn_kernel(const float* __restrict__ qkv,
            __nv_bfloat16* __restrict__ chi, __nv_bfloat16* __restrict__ clo) {
    extern __shared__ float smemf[];
    float* Ks = smemf;
    float* Vs = smemf + BK * HD_;
    int h  = blockIdx.y;
    int qb = blockIdx.x;
    int tid = threadIdx.x;
    int q = tid >> 3;
    int c = tid & 7;
    int tq = qb * BQ + q;

    const float* qrow = qkv + (size_t)tq * (3 * DM_) + h * HD_;
    float qreg[32];
#pragma unroll
    for (int j = 0; j < 8; j++) {
        float4 v = *(const float4*)(qrow + c * 4 + 32 * j);
        qreg[4 * j + 0] = v.x; qreg[4 * j + 1] = v.y;
        qreg[4 * j + 2] = v.z; qreg[4 * j + 3] = v.w;
    }
    float acc[32];
#pragma unroll
    for (int j = 0; j < 32; j++) acc[j] = 0.f;
    float m = -CUDART_INF_F, l = 0.f;
    const float scale = 0.0625f;

    int ntiles = qb + 1;
    for (int kt = 0; kt < ntiles; ++kt) {
        __syncthreads();
        {
            int r  = tid >> 3;
            int cc = tid & 7;
            const float* krow = qkv + (size_t)(kt * BK + r) * (3 * DM_) + DM_ + h * HD_;
            const float* vrow = krow + DM_;
#pragma unroll
            for (int j = 0; j < 8; j++) {
                *(float4*)(Ks + r * HD_ + cc * 4 + 32 * j) = *(const float4*)(krow + cc * 4 + 32 * j);
                *(float4*)(Vs + r * HD_ + cc * 4 + 32 * j) = *(const float4*)(vrow + cc * 4 + 32 * j);
            }
        }
        __syncthreads();

        float s[32];
        float mloc = -CUDART_INF_F;
#pragma unroll 4
        for (int kk = 0; kk < BK; ++kk) {
            const float* kr = Ks + kk * HD_;
            float part = 0.f;
#pragma unroll
            for (int j = 0; j < 8; j++) {
                float4 v = *(const float4*)(kr + c * 4 + 32 * j);
                part += qreg[4 * j] * v.x + qreg[4 * j + 1] * v.y
                      + qreg[4 * j + 2] * v.z + qreg[4 * j + 3] * v.w;
            }
            part += __shfl_xor_sync(0xffffffffu, part, 1);
            part += __shfl_xor_sync(0xffffffffu, part, 2);
            part += __shfl_xor_sync(0xffffffffu, part, 4);
            part *= scale;
            int tk = kt * BK + kk;
            if (tk > tq) part = -CUDART_INF_F;
            s[kk] = part;
            mloc = fmaxf(mloc, part);
        }
        float mnew  = fmaxf(m, mloc);
        float alpha = __expf(m - mnew);
        l *= alpha;
#pragma unroll
        for (int j = 0; j < 32; j++) acc[j] *= alpha;
#pragma unroll 4
        for (int kk = 0; kk < BK; ++kk) {
            float p = __expf(s[kk] - mnew);
            l += p;
            const float* vr = Vs + kk * HD_;
#pragma unroll
            for (int j = 0; j < 8; j++) {
                float4 v = *(const float4*)(vr + c * 4 + 32 * j);
                acc[4 * j + 0] += p * v.x;
                acc[4 * j + 1] += p * v.y;
                acc[4 * j + 2] += p * v.z;
                acc[4 * j + 3] += p * v.w;
            }
        }
        m = mnew;
    }

    float invl = 1.0f / l;
    size_t obase = (size_t)tq * DM_ + h * HD_;
#pragma unroll
    for (int j = 0; j < 8; j++) {
#pragma unroll
        for (int ii = 0; ii < 4; ii++) {
            float v = acc[4 * j + ii] * invl;
            size_t o = obase + c * 4 + 32 * j + ii;
            split_store(v, chi + o, clo + o);
        }
    }
}

// ---------------- launch ----------------
extern "C" void kernel_launch(void* const* d_in, const int* in_sizes, int n_in,
                              void* d_out, int out_size) {
    const int*   positions = (const int*)  d_in[0];
    const float* hidden    = (const float*)d_in[1];
    const float* ln_g      = (const float*)d_in[2];
    const float* ln_b      = (const float*)d_in[3];
    const float* w_qkv     = (const float*)d_in[4];
    const float* w_out     = (const float*)d_in[5];
    const float* w_fc_in   = (const float*)d_in[6];
    const float* b_fc_in   = (const float*)d_in[7];
    const float* w_fc_out  = (const float*)d_in[8];
    const float* b_fc_out  = (const float*)d_in[9];
    float* out = (float*)d_out;

    __nv_bfloat16 *wqh, *wql, *woh, *wol, *wih, *wil, *wfh, *wfl;
    __nv_bfloat16 *lnh, *lnl, *ach, *acl, *cxh, *cxl;
    float *p_qkv;
    cudaGetSymbolAddress((void**)&wqh, g_wqkvT_hi);  cudaGetSymbolAddress((void**)&wql, g_wqkvT_lo);
    cudaGetSymbolAddress((void**)&woh, g_woutT_hi);  cudaGetSymbolAddress((void**)&wol, g_woutT_lo);
    cudaGetSymbolAddress((void**)&wih, g_wfciT_hi);  cudaGetSymbolAddress((void**)&wil, g_wfciT_lo);
    cudaGetSymbolAddress((void**)&wfh, g_wfcoT_hi);  cudaGetSymbolAddress((void**)&wfl, g_wfcoT_lo);
    cudaGetSymbolAddress((void**)&lnh, g_ln_hi);     cudaGetSymbolAddress((void**)&lnl, g_ln_lo);
    cudaGetSymbolAddress((void**)&ach, g_act_hi);    cudaGetSymbolAddress((void**)&acl, g_act_lo);
    cudaGetSymbolAddress((void**)&cxh, g_ctx_hi);    cudaGetSymbolAddress((void**)&cxl, g_ctx_lo);
    cudaGetSymbolAddress((void**)&p_qkv, g_qkv);

    cudaFuncSetAttribute(mma_gemm<0>, cudaFuncAttributeMaxDynamicSharedMemorySize, GEMM_SMEM);
    cudaFuncSetAttribute(mma_gemm<1>, cudaFuncAttributeMaxDynamicSharedMemorySize, GEMM_SMEM);
    cudaFuncSetAttribute(mma_gemm<2>, cudaFuncAttributeMaxDynamicSharedMemorySize, GEMM_SMEM);
    cudaFuncSetAttribute(mma_gemm<3>, cudaFuncAttributeMaxDynamicSharedMemorySize, GEMM_SMEM);
    cudaFuncSetAttribute(attn_kernel, cudaFuncAttributeMaxDynamicSharedMemorySize,
                         2 * BK * HD_ * (int)sizeof(float));

    dim3 cb(32, 8);
    convT_kernel<<<dim3(3 * DM_ / 32, DM_ / 32), cb>>>(w_qkv,   wqh, wql, DM_,  3 * DM_);
    convT_kernel<<<dim3(DM_ / 32,     DM_ / 32), cb>>>(w_out,   woh, wol, DM_,  DM_);
    convT_kernel<<<dim3(DFF_ / 32,    DM_ / 32), cb>>>(w_fc_in, wih, wil, DM_,  DFF_);
    convT_kernel<<<dim3(DM_ / 32,    DFF_ / 32), cb>>>(w_fc_out,wfh, wfl, DFF_, DM_);

    ln_kernel<<<T_, 256>>>(hidden, ln_g, ln_b, lnh, lnl);

    // QKV GEMM -> fp32 qkv
    mma_gemm<0><<<(T_ / 128) * (3 * DM_ / 128), 256, GEMM_SMEM>>>(
        lnh, lnl, wqh, wql, p_qkv, nullptr, nullptr, nullptr, nullptr,
        T_, 3 * DM_, DM_);

    rope_kernel<<<(T_ * H_ * 64) / 256, 256>>>(p_qkv, positions);

    attn_kernel<<<dim3(T_ / BQ, H_), 256, 2 * BK * HD_ * sizeof(float)>>>(p_qkv, cxh, cxl);

    // fc_in + gelu -> act hi/lo
    mma_gemm<1><<<(T_ / 128) * (DFF_ / 128), 256, GEMM_SMEM>>>(
        lnh, lnl, wih, wil, nullptr, ach, acl, b_fc_in, nullptr,
        T_, DFF_, DM_);

    // fc_out + bias + residual -> out
    mma_gemm<2><<<(T_ / 128) * (DM_ / 128), 256, GEMM_SMEM>>>(
        ach, acl, wfh, wfl, out, nullptr, nullptr, b_fc_out, hidden,
        T_, DM_, DFF_);

    // attention out-proj, accumulate into out
    mma_gemm<3><<<(T_ / 128) * (DM_ / 128), 256, GEMM_SMEM>>>(
        cxh, cxl, woh, wol, out, nullptr, nullptr, nullptr, nullptr,
        T_, DM_, DM_);
}

// round 12
// speedup vs baseline: 2.0112x; 1.0994x over previous
#include <cuda_runtime.h>
#include <cuda_bf16.h>
#include <math.h>
#include <math_constants.h>
#include <cstdint>

#define T_   2048
#define DM_  4096
#define H_   16
#define HD_  256
#define RD_  64
#define DFF_ 16384

// ---------------- scratch (device globals) ----------------
__device__ __nv_bfloat16 g_wqkvT_hi[(size_t)3*DM_*DM_];
__device__ __nv_bfloat16 g_wqkvT_lo[(size_t)3*DM_*DM_];
__device__ __nv_bfloat16 g_woutT_hi[(size_t)DM_*DM_];
__device__ __nv_bfloat16 g_woutT_lo[(size_t)DM_*DM_];
__device__ __nv_bfloat16 g_wfciT_hi[(size_t)DFF_*DM_];
__device__ __nv_bfloat16 g_wfciT_lo[(size_t)DFF_*DM_];
__device__ __nv_bfloat16 g_wfcoT_hi[(size_t)DM_*DFF_];
__device__ __nv_bfloat16 g_wfcoT_lo[(size_t)DM_*DFF_];
__device__ __nv_bfloat16 g_ln_hi[(size_t)T_*DM_];
__device__ __nv_bfloat16 g_ln_lo[(size_t)T_*DM_];
__device__ __nv_bfloat16 g_act_hi[(size_t)T_*DFF_];
__device__ __nv_bfloat16 g_act_lo[(size_t)T_*DFF_];
__device__ __nv_bfloat16 g_ctx_hi[(size_t)T_*DM_];
__device__ __nv_bfloat16 g_ctx_lo[(size_t)T_*DM_];
__device__ float g_qkv[(size_t)T_*3*DM_];
__device__ float g_attnout[(size_t)T_*DM_];

// ---------------- PTX helpers (baseline features only) --------
__device__ __forceinline__ uint32_t smem_u32(const void* p) {
    uint32_t a;
    asm("{ .reg .u64 t; cvta.to.shared.u64 t, %1; cvt.u32.u64 %0, t; }" : "=r"(a) : "l"(p));
    return a;
}
__device__ __forceinline__ void cp_async16(uint32_t d, const void* g) {
    asm volatile("cp.async.cg.shared.global [%0], [%1], 16;" :: "r"(d), "l"(g));
}
#define CP_COMMIT()  asm volatile("cp.async.commit_group;" ::: "memory")
#define CP_WAIT1()   asm volatile("cp.async.wait_group 1;" ::: "memory")

__device__ __forceinline__ void ldsm4(uint32_t* r, uint32_t addr) {
    asm volatile("ldmatrix.sync.aligned.m8n8.x4.shared.b16 {%0,%1,%2,%3}, [%4];"
                 : "=r"(r[0]), "=r"(r[1]), "=r"(r[2]), "=r"(r[3]) : "r"(addr));
}
__device__ __forceinline__ void mma16816(float* c, const uint32_t* a,
                                         uint32_t b0, uint32_t b1) {
    asm volatile("mma.sync.aligned.m16n8k16.row.col.f32.bf16.bf16.f32 "
                 "{%0,%1,%2,%3}, {%4,%5,%6,%7}, {%8,%9}, {%0,%1,%2,%3};"
                 : "+f"(c[0]), "+f"(c[1]), "+f"(c[2]), "+f"(c[3])
                 : "r"(a[0]), "r"(a[1]), "r"(a[2]), "r"(a[3]), "r"(b0), "r"(b1));
}

__device__ __forceinline__ void split_store(float v, __nv_bfloat16* ph, __nv_bfloat16* pl) {
    __nv_bfloat16 h = __float2bfloat16(v);
    *ph = h;
    *pl = __float2bfloat16(v - __bfloat162float(h));
}

// ---------------- weight transpose + bf16 split ----------------
__global__ void convT_kernel(const float* __restrict__ W,
                             __nv_bfloat16* __restrict__ hi,
                             __nv_bfloat16* __restrict__ lo,
                             int Krows, int Ncols) {
    __shared__ float tile[32][33];
    int n0 = blockIdx.x * 32, k0 = blockIdx.y * 32;
    int tx = threadIdx.x, ty = threadIdx.y;
#pragma unroll
    for (int i = 0; i < 4; i++)
        tile[ty + 8 * i][tx] = W[(size_t)(k0 + ty + 8 * i) * Ncols + n0 + tx];
    __syncthreads();
#pragma unroll
    for (int i = 0; i < 4; i++) {
        int r = ty + 8 * i;
        float v = tile[tx][r];
        size_t o = (size_t)(n0 + r) * Krows + k0 + tx;
        __nv_bfloat16 h = __float2bfloat16(v);
        hi[o] = h;
        lo[o] = __float2bfloat16(v - __bfloat162float(h));
    }
}

// ---------------- LayerNorm -> bf16 hi/lo ----------------
__global__ void ln_kernel(const float* __restrict__ x,
                          const float* __restrict__ gamma,
                          const float* __restrict__ beta,
                          __nv_bfloat16* __restrict__ ohi,
                          __nv_bfloat16* __restrict__ olo) {
    int row = blockIdx.x;
    const float4* xr = (const float4*)(x + (size_t)row * DM_);
    float4 v[4];
    float sum = 0.f, sq = 0.f;
#pragma unroll
    for (int i = 0; i < 4; i++) {
        v[i] = xr[threadIdx.x + 256 * i];
        sum += v[i].x + v[i].y + v[i].z + v[i].w;
        sq  += v[i].x * v[i].x + v[i].y * v[i].y + v[i].z * v[i].z + v[i].w * v[i].w;
    }
#pragma unroll
    for (int o = 16; o; o >>= 1) {
        sum += __shfl_xor_sync(0xffffffffu, sum, o);
        sq  += __shfl_xor_sync(0xffffffffu, sq,  o);
    }
    __shared__ float ssum[8], ssq[8];
    int warp = threadIdx.x >> 5, lane = threadIdx.x & 31;
    if (lane == 0) { ssum[warp] = sum; ssq[warp] = sq; }
    __syncthreads();
    sum = 0.f; sq = 0.f;
#pragma unroll
    for (int i = 0; i < 8; i++) { sum += ssum[i]; sq += ssq[i]; }
    float mu  = sum * (1.0f / DM_);
    float var = sq * (1.0f / DM_) - mu * mu;
    float inv = rsqrtf(var + 1e-5f);
    const float4* g4 = (const float4*)gamma;
    const float4* b4 = (const float4*)beta;
#pragma unroll
    for (int i = 0; i < 4; i++) {
        int idx = threadIdx.x + 256 * i;
        float4 g = g4[idx], b = b4[idx];
        size_t base = (size_t)row * DM_ + idx * 4;
        split_store((v[i].x - mu) * inv * g.x + b.x, ohi + base + 0, olo + base + 0);
        split_store((v[i].y - mu) * inv * g.y + b.y, ohi + base + 1, olo + base + 1);
        split_store((v[i].z - mu) * inv * g.z + b.z, ohi + base + 2, olo + base + 2);
        split_store((v[i].w - mu) * inv * g.w + b.w, ohi + base + 3, olo + base + 3);
    }
}

// ---------------- RoPE (GPT-J interleaved) ----------------
__global__ void rope_kernel(float* __restrict__ qkv, const int* __restrict__ positions) {
    int idx = blockIdx.x * blockDim.x + threadIdx.x;
    int i     = idx & 31;
    int which = (idx >> 5) & 1;
    int h     = (idx >> 6) & 15;
    int t     = idx >> 10;
    float inv = (float)pow(10000.0, -(double)i / 32.0);
    float ang = (float)positions[t] * inv;
    float s, c;
    sincosf(ang, &s, &c);
    float* p = qkv + (size_t)t * (3 * DM_) + (size_t)which * DM_ + h * HD_ + 2 * i;
    float x1 = p[0], x2 = p[1];
    p[0] = x1 * c - x2 * s;
    p[1] = x2 * c + x1 * s;
}

__device__ __forceinline__ float gelu_tanh(float x) {
    float x3 = x * x * x;
    float t  = tanhf(0.7978845608028654f * (x + 0.044715f * x3));
    return 0.5f * x * (1.0f + t);
}

// ---------------- final merge: out += attnout ----------------
__global__ void add_kernel(float* __restrict__ out, const float* __restrict__ a) {
    int i = blockIdx.x * blockDim.x + threadIdx.x;
    float4 o = ((const float4*)out)[i];
    float4 v = ((const float4*)a)[i];
    o.x += v.x; o.y += v.y; o.z += v.z; o.w += v.w;
    ((float4*)out)[i] = o;
}

// ---------------- mma.sync split-bf16 GEMM ----------------
// CTA 128x128, 256 threads, warp tile 64x32 (2x4 warp grid), KC=32.
// 3-stage cp.async pipeline with XOR-swizzled 64B rows, 2 CTAs/SM.
// EPI: 0 store fp32; 1 gelu(v+bias)->Ohi/Olo; 2 v+bias+res->C; 3 C += v
#define KC 32
#define ARR_BYTES 8192                        // 128 rows x 64B
#define AHI_OFF 0
#define ALO_OFF 8192
#define BHI_OFF 16384
#define BLO_OFF 24576
#define STAGE_BYTES 32768
#define NSTAGE 3
#define GEMM_SMEM (NSTAGE * STAGE_BYTES)      // 98304

template <int EPI>
__global__ void __launch_bounds__(256, 2)
mma_gemm(const __nv_bfloat16* __restrict__ Ahi, const __nv_bfloat16* __restrict__ Alo,
         const __nv_bfloat16* __restrict__ Bhi, const __nv_bfloat16* __restrict__ Blo,
         float* __restrict__ C,
         __nv_bfloat16* __restrict__ Ohi, __nv_bfloat16* __restrict__ Olo,
         const float* __restrict__ bias, const float* __restrict__ res,
         int M, int N, int K) {
    extern __shared__ char smem[];
    const uint32_t sb0 = smem_u32(smem);
    int tid = threadIdx.x;
    int lane = tid & 31, wid = tid >> 5;
    int wm = wid >> 2, wn = wid & 3;

    // supertile rasterization (groups of 8 N-blocks) for L2 reuse
    int nbn = N / 128, nbm = M / 128;
    const int SWT = 8;
    int per = SWT * nbm;
    int ggrp = blockIdx.x / per, rem = blockIdx.x - ggrp * per;
    int bn0 = ggrp * SWT;
    int w = nbn - bn0; if (w > SWT) w = SWT;
    int bn = bn0 + rem % w;
    int bm = rem / w;

    float acc[4][4][4];
#pragma unroll
    for (int i = 0; i < 4; i++)
#pragma unroll
        for (int j = 0; j < 4; j++)
#pragma unroll
            for (int q = 0; q < 4; q++) acc[i][j][q] = 0.f;

    auto load_stage = [&](int s, int k0) {
        uint32_t sb = sb0 + s * STAGE_BYTES;
#pragma unroll
        for (int j = 0; j < 2; j++) {
            int id  = tid + 256 * j;
            int row = id >> 2, c = id & 3;
            uint32_t d = row * 64 + ((c ^ ((row >> 1) & 3)) << 4);
            size_t goA = (size_t)(bm * 128 + row) * K + k0 + c * 8;
            size_t goB = (size_t)(bn * 128 + row) * K + k0 + c * 8;
            cp_async16(sb + AHI_OFF + d, Ahi + goA);
            cp_async16(sb + ALO_OFF + d, Alo + goA);
            cp_async16(sb + BHI_OFF + d, Bhi + goB);
            cp_async16(sb + BLO_OFF + d, Blo + goB);
        }
    };

    load_stage(0, 0); CP_COMMIT();
    load_stage(1, KC); CP_COMMIT();

    int hi4 = lane >> 4;
    int rA[4], swA[4], rB0, rB1, swB0, swB1;
#pragma unroll
    for (int i = 0; i < 4; i++) {
        int r = wm * 64 + i * 16 + (lane & 15);
        rA[i] = r * 64;
        swA[i] = (r >> 1) & 3;
    }
    {
        int r0 = wn * 32 + (lane & 15);
        int r1 = r0 + 16;
        rB0 = r0 * 64; swB0 = (r0 >> 1) & 3;
        rB1 = r1 * 64; swB1 = (r1 >> 1) & 3;
    }

    int nk = K / KC;
    int st = 0, ld = 2;
    for (int kc = 0; kc < nk; kc++) {
        CP_WAIT1();
        __syncthreads();
        if (kc + 2 < nk) load_stage(ld, (kc + 2) * KC);
        CP_COMMIT();
        uint32_t base = sb0 + st * STAGE_BYTES;
#pragma unroll
        for (int ks = 0; ks < 2; ks++) {
            int c = ks * 2 + hi4;
            uint32_t bh[8], bl[8];
            ldsm4(bh,     base + BHI_OFF + rB0 + ((c ^ swB0) << 4));
            ldsm4(bh + 4, base + BHI_OFF + rB1 + ((c ^ swB1) << 4));
            ldsm4(bl,     base + BLO_OFF + rB0 + ((c ^ swB0) << 4));
            ldsm4(bl + 4, base + BLO_OFF + rB1 + ((c ^ swB1) << 4));
#pragma unroll
            for (int i = 0; i < 4; i++) {
                uint32_t ah[4], al[4];
                ldsm4(ah, base + AHI_OFF + rA[i] + ((c ^ swA[i]) << 4));
                ldsm4(al, base + ALO_OFF + rA[i] + ((c ^ swA[i]) << 4));
#pragma unroll
                for (int j = 0; j < 4; j++) {
                    int j2 = j >> 1, ss = j & 1;
                    uint32_t b0h = bh[j2 * 4 + ss], b1h = bh[j2 * 4 + ss + 2];
                    uint32_t b0l = bl[j2 * 4 + ss], b1l = bl[j2 * 4 + ss + 2];
                    mma16816(acc[i][j], ah, b0h, b1h);
                    mma16816(acc[i][j], ah, b0l, b1l);
                    mma16816(acc[i][j], al, b0h, b1h);
                }
            }
        }
        st = (st == 2) ? 0 : st + 1;
        ld = (ld == 2) ? 0 : ld + 1;
    }

    int gq = lane >> 2, cc = lane & 3;
#pragma unroll
    for (int i = 0; i < 4; i++) {
#pragma unroll
        for (int j = 0; j < 4; j++) {
            int row = bm * 128 + wm * 64 + i * 16 + gq;
            int col = bn * 128 + wn * 32 + j * 8 + 2 * cc;
            float* a4 = acc[i][j];
#pragma unroll
            for (int half = 0; half < 2; half++) {
                int r = row + 8 * half;
                float v0 = a4[2 * half], v1 = a4[2 * half + 1];
                size_t base = (size_t)r * N + col;
                if (EPI == 0) {
                    *(float2*)(C + base) = make_float2(v0, v1);
                } else if (EPI == 1) {
                    float g0 = gelu_tanh(v0 + bias[col]);
                    float g1 = gelu_tanh(v1 + bias[col + 1]);
                    split_store(g0, Ohi + base, Olo + base);
                    split_store(g1, Ohi + base + 1, Olo + base + 1);
                } else if (EPI == 2) {
                    float2 rr = *(const float2*)(res + base);
                    *(float2*)(C + base) = make_float2(v0 + bias[col] + rr.x,
                                                       v1 + bias[col + 1] + rr.y);
                } else {
                    float2 cur = *(float2*)(C + base);
                    *(float2*)(C + base) = make_float2(cur.x + v0, cur.y + v1);
                }
            }
        }
    }
}

// ---------------- causal flash attention (fp32), ctx -> bf16 hi/lo ----------------
#define BQ 32
#define BK 32
__global__ void __launch_bounds__(256)
attn_kernel(const float* __restrict__ qkv,
            __nv_bfloat16* __restrict__ chi, __nv_bfloat16* __restrict__ clo) {
    extern __shared__ float smemf[];
    float* Ks = smemf;
    float* Vs = smemf + BK * HD_;
    int h  = blockIdx.y;
    int qb = blockIdx.x;
    int tid = threadIdx.x;
    int q = tid >> 3;
    int c = tid & 7;
    int tq = qb * BQ + q;

    const float* qrow = qkv + (size_t)tq * (3 * DM_) + h * HD_;
    float qreg[32];
#pragma unroll
    for (int j = 0; j < 8; j++) {
        float4 v = *(const float4*)(qrow + c * 4 + 32 * j);
        qreg[4 * j + 0] = v.x; qreg[4 * j + 1] = v.y;
        qreg[4 * j + 2] = v.z; qreg[4 * j + 3] = v.w;
    }
    float acc[32];
#pragma unroll
    for (int j = 0; j < 32; j++) acc[j] = 0.f;
    float m = -CUDART_INF_F, l = 0.f;
    const float scale = 0.0625f;

    int ntiles = qb + 1;
    for (int kt = 0; kt < ntiles; ++kt) {
        __syncthreads();
        {
            int r  = tid >> 3;
            int cc = tid & 7;
            const float* krow = qkv + (size_t)(kt * BK + r) * (3 * DM_) + DM_ + h * HD_;
            const float* vrow = krow + DM_;
#pragma unroll
            for (int j = 0; j < 8; j++) {
                *(float4*)(Ks + r * HD_ + cc * 4 + 32 * j) = *(const float4*)(krow + cc * 4 + 32 * j);
                *(float4*)(Vs + r * HD_ + cc * 4 + 32 * j) = *(const float4*)(vrow + cc * 4 + 32 * j);
            }
        }
        __syncthreads();

        float s[32];
        float mloc = -CUDART_INF_F;
#pragma unroll 4
        for (int kk = 0; kk < BK; ++kk) {
            const float* kr = Ks + kk * HD_;
            float part = 0.f;
#pragma unroll
            for (int j = 0; j < 8; j++) {
                float4 v = *(const float4*)(kr + c * 4 + 32 * j);
                part += qreg[4 * j] * v.x + qreg[4 * j + 1] * v.y
                      + qreg[4 * j + 2] * v.z + qreg[4 * j + 3] * v.w;
            }
            part += __shfl_xor_sync(0xffffffffu, part, 1);
            part += __shfl_xor_sync(0xffffffffu, part, 2);
            part += __shfl_xor_sync(0xffffffffu, part, 4);
            part *= scale;
            int tk = kt * BK + kk;
            if (tk > tq) part = -CUDART_INF_F;
            s[kk] = part;
            mloc = fmaxf(mloc, part);
        }
        float mnew  = fmaxf(m, mloc);
        float alpha = __expf(m - mnew);
        l *= alpha;
#pragma unroll
        for (int j = 0; j < 32; j++) acc[j] *= alpha;
#pragma unroll 4
        for (int kk = 0; kk < BK; ++kk) {
            float p = __expf(s[kk] - mnew);
            l += p;
            const float* vr = Vs + kk * HD_;
#pragma unroll
            for (int j = 0; j < 8; j++) {
                float4 v = *(const float4*)(vr + c * 4 + 32 * j);
                acc[4 * j + 0] += p * v.x;
                acc[4 * j + 1] += p * v.y;
                acc[4 * j + 2] += p * v.z;
                acc[4 * j + 3] += p * v.w;
            }
        }
        m = mnew;
    }

    float invl = 1.0f / l;
    size_t obase = (size_t)tq * DM_ + h * HD_;
#pragma unroll
    for (int j = 0; j < 8; j++) {
#pragma unroll
        for (int ii = 0; ii < 4; ii++) {
            float v = acc[4 * j + ii] * invl;
            size_t o = obase + c * 4 + 32 * j + ii;
            split_store(v, chi + o, clo + o);
        }
    }
}

// ---------------- launch ----------------
extern "C" void kernel_launch(void* const* d_in, const int* in_sizes, int n_in,
                              void* d_out, int out_size) {
    const int*   positions = (const int*)  d_in[0];
    const float* hidden    = (const float*)d_in[1];
    const float* ln_g      = (const float*)d_in[2];
    const float* ln_b      = (const float*)d_in[3];
    const float* w_qkv     = (const float*)d_in[4];
    const float* w_out     = (const float*)d_in[5];
    const float* w_fc_in   = (const float*)d_in[6];
    const float* b_fc_in   = (const float*)d_in[7];
    const float* w_fc_out  = (const float*)d_in[8];
    const float* b_fc_out  = (const float*)d_in[9];
    float* out = (float*)d_out;

    __nv_bfloat16 *wqh, *wql, *woh, *wol, *wih, *wil, *wfh, *wfl;
    __nv_bfloat16 *lnh, *lnl, *ach, *acl, *cxh, *cxl;
    float *p_qkv, *p_att;
    cudaGetSymbolAddress((void**)&wqh, g_wqkvT_hi);  cudaGetSymbolAddress((void**)&wql, g_wqkvT_lo);
    cudaGetSymbolAddress((void**)&woh, g_woutT_hi);  cudaGetSymbolAddress((void**)&wol, g_woutT_lo);
    cudaGetSymbolAddress((void**)&wih, g_wfciT_hi);  cudaGetSymbolAddress((void**)&wil, g_wfciT_lo);
    cudaGetSymbolAddress((void**)&wfh, g_wfcoT_hi);  cudaGetSymbolAddress((void**)&wfl, g_wfcoT_lo);
    cudaGetSymbolAddress((void**)&lnh, g_ln_hi);     cudaGetSymbolAddress((void**)&lnl, g_ln_lo);
    cudaGetSymbolAddress((void**)&ach, g_act_hi);    cudaGetSymbolAddress((void**)&acl, g_act_lo);
    cudaGetSymbolAddress((void**)&cxh, g_ctx_hi);    cudaGetSymbolAddress((void**)&cxl, g_ctx_lo);
    cudaGetSymbolAddress((void**)&p_qkv, g_qkv);
    cudaGetSymbolAddress((void**)&p_att, g_attnout);

    cudaFuncSetAttribute(mma_gemm<0>, cudaFuncAttributeMaxDynamicSharedMemorySize, GEMM_SMEM);
    cudaFuncSetAttribute(mma_gemm<1>, cudaFuncAttributeMaxDynamicSharedMemorySize, GEMM_SMEM);
    cudaFuncSetAttribute(mma_gemm<2>, cudaFuncAttributeMaxDynamicSharedMemorySize, GEMM_SMEM);
    cudaFuncSetAttribute(attn_kernel, cudaFuncAttributeMaxDynamicSharedMemorySize,
                         2 * BK * HD_ * (int)sizeof(float));

    // streams/events created once (outside any capture); handles are stateless wrt work
    static cudaStream_t s1 = nullptr, s2 = nullptr;
    static cudaEvent_t evFork = nullptr, evLN = nullptr, evJoin1 = nullptr, evJoin2 = nullptr;
    if (!s1) {
        cudaStreamCreateWithFlags(&s1, cudaStreamNonBlocking);
        cudaStreamCreateWithFlags(&s2, cudaStreamNonBlocking);
        cudaEventCreateWithFlags(&evFork,  cudaEventDisableTiming);
        cudaEventCreateWithFlags(&evLN,    cudaEventDisableTiming);
        cudaEventCreateWithFlags(&evJoin1, cudaEventDisableTiming);
        cudaEventCreateWithFlags(&evJoin2, cudaEventDisableTiming);
    }

    dim3 cb(32, 8);

    // fork both chains off the caller's stream
    cudaEventRecord(evFork, 0);
    cudaStreamWaitEvent(s1, evFork, 0);
    cudaStreamWaitEvent(s2, evFork, 0);

    // ---- chain A prep (s1): attention-path weights + LN ----
    convT_kernel<<<dim3(3 * DM_ / 32, DM_ / 32), cb, 0, s1>>>(w_qkv, wqh, wql, DM_, 3 * DM_);
    convT_kernel<<<dim3(DM_ / 32,     DM_ / 32), cb, 0, s1>>>(w_out, woh, wol, DM_, DM_);
    ln_kernel<<<T_, 256, 0, s1>>>(hidden, ln_g, ln_b, lnh, lnl);
    cudaEventRecord(evLN, s1);

    // ---- chain B (s2): MLP weights, then fc_in -> fc_out ----
    convT_kernel<<<dim3(DFF_ / 32, DM_ / 32), cb, 0, s2>>>(w_fc_in,  wih, wil, DM_,  DFF_);
    convT_kernel<<<dim3(DM_ / 32, DFF_ / 32), cb, 0, s2>>>(w_fc_out, wfh, wfl, DFF_, DM_);
    cudaStreamWaitEvent(s2, evLN, 0);
    mma_gemm<1><<<(T_ / 128) * (DFF_ / 128), 256, GEMM_SMEM, s2>>>(
        lnh, lnl, wih, wil, nullptr, ach, acl, b_fc_in, nullptr, T_, DFF_, DM_);
    mma_gemm<2><<<(T_ / 128) * (DM_ / 128), 256, GEMM_SMEM, s2>>>(
        ach, acl, wfh, wfl, out, nullptr, nullptr, b_fc_out, hidden, T_, DM_, DFF_);
    cudaEventRecord(evJoin2, s2);

    // ---- chain A (s1): QKV -> RoPE -> attention -> out-proj ----
    mma_gemm<0><<<(T_ / 128) * (3 * DM_ / 128), 256, GEMM_SMEM, s1>>>(
        lnh, lnl, wqh, wql, p_qkv, nullptr, nullptr, nullptr, nullptr, T_, 3 * DM_, DM_);
    rope_kernel<<<(T_ * H_ * 64) / 256, 256, 0, s1>>>(p_qkv, positions);
    attn_kernel<<<dim3(T_ / BQ, H_), 256, 2 * BK * HD_ * sizeof(float), s1>>>(p_qkv, cxh, cxl);
    mma_gemm<0><<<(T_ / 128) * (DM_ / 128), 256, GEMM_SMEM, s1>>>(
        cxh, cxl, woh, wol, p_att, nullptr, nullptr, nullptr, nullptr, T_, DM_, DM_);
    cudaEventRecord(evJoin1, s1);

    // ---- join on the caller's stream, final merge ----
    cudaStreamWaitEvent(0, evJoin1, 0);
    cudaStreamWaitEvent(0, evJoin2, 0);
    add_kernel<<<(T_ * DM_ / 4) / 256, 256>>>(out, p_att);
}

// round 15
// speedup vs baseline: 2.4345x; 1.2105x over previous
#include <cuda_runtime.h>
#include <cuda_bf16.h>
#include <math.h>
#include <math_constants.h>
#include <cstdint>

#define T_   2048
#define DM_  4096
#define H_   16
#define HD_  256
#define RD_  64
#define DFF_ 16384

// ---------------- scratch (device globals) ----------------
__device__ __nv_bfloat16 g_wqkvT_hi[(size_t)3*DM_*DM_];
__device__ __nv_bfloat16 g_wqkvT_lo[(size_t)3*DM_*DM_];
__device__ __nv_bfloat16 g_woutT_hi[(size_t)DM_*DM_];
__device__ __nv_bfloat16 g_woutT_lo[(size_t)DM_*DM_];
__device__ __nv_bfloat16 g_wfciT_hi[(size_t)DFF_*DM_];
__device__ __nv_bfloat16 g_wfciT_lo[(size_t)DFF_*DM_];
__device__ __nv_bfloat16 g_wfcoT_hi[(size_t)DM_*DFF_];
__device__ __nv_bfloat16 g_wfcoT_lo[(size_t)DM_*DFF_];
__device__ __nv_bfloat16 g_ln_hi[(size_t)T_*DM_];
__device__ __nv_bfloat16 g_ln_lo[(size_t)T_*DM_];
__device__ __nv_bfloat16 g_act_hi[(size_t)T_*DFF_];
__device__ __nv_bfloat16 g_act_lo[(size_t)T_*DFF_];
__device__ __nv_bfloat16 g_ctx_hi[(size_t)T_*DM_];
__device__ __nv_bfloat16 g_ctx_lo[(size_t)T_*DM_];
__device__ float g_qkv[(size_t)T_*3*DM_];
__device__ float g_attnout[(size_t)T_*DM_];
// attention operand buffers ([H][T][HD] for q,k; [H][HD][T] for v transposed)
__device__ __nv_bfloat16 g_qh[(size_t)T_*DM_];
__device__ __nv_bfloat16 g_ql[(size_t)T_*DM_];
__device__ __nv_bfloat16 g_kh[(size_t)T_*DM_];
__device__ __nv_bfloat16 g_kl[(size_t)T_*DM_];
__device__ __nv_bfloat16 g_vth[(size_t)T_*DM_];
__device__ __nv_bfloat16 g_vtl[(size_t)T_*DM_];

// ---------------- PTX helpers (baseline features only) --------
__device__ __forceinline__ uint32_t smem_u32(const void* p) {
    uint32_t a;
    asm("{ .reg .u64 t; cvta.to.shared.u64 t, %1; cvt.u32.u64 %0, t; }" : "=r"(a) : "l"(p));
    return a;
}
__device__ __forceinline__ void cp_async16(uint32_t d, const void* g) {
    asm volatile("cp.async.cg.shared.global [%0], [%1], 16;" :: "r"(d), "l"(g));
}
#define CP_COMMIT()  asm volatile("cp.async.commit_group;" ::: "memory")
#define CP_WAIT1()   asm volatile("cp.async.wait_group 1;" ::: "memory")
#define CP_WAIT0()   asm volatile("cp.async.wait_group 0;" ::: "memory")

__device__ __forceinline__ void ldsm4(uint32_t* r, uint32_t addr) {
    asm volatile("ldmatrix.sync.aligned.m8n8.x4.shared.b16 {%0,%1,%2,%3}, [%4];"
                 : "=r"(r[0]), "=r"(r[1]), "=r"(r[2]), "=r"(r[3]) : "r"(addr));
}
__device__ __forceinline__ void mma16816(float* c, const uint32_t* a,
                                         uint32_t b0, uint32_t b1) {
    asm volatile("mma.sync.aligned.m16n8k16.row.col.f32.bf16.bf16.f32 "
                 "{%0,%1,%2,%3}, {%4,%5,%6,%7}, {%8,%9}, {%0,%1,%2,%3};"
                 : "+f"(c[0]), "+f"(c[1]), "+f"(c[2]), "+f"(c[3])
                 : "r"(a[0]), "r"(a[1]), "r"(a[2]), "r"(a[3]), "r"(b0), "r"(b1));
}
__device__ __forceinline__ uint32_t pack_bf16x2(float lo, float hi) {
    uint32_t r;
    asm("cvt.rn.bf16x2.f32 %0, %1, %2;" : "=r"(r) : "f"(hi), "f"(lo));
    return r;
}
__device__ __forceinline__ void split_store(float v, __nv_bfloat16* ph, __nv_bfloat16* pl) {
    __nv_bfloat16 h = __float2bfloat16(v);
    *ph = h;
    *pl = __float2bfloat16(v - __bfloat162float(h));
}

// ---------------- weight transpose + bf16 split ----------------
__global__ void convT_kernel(const float* __restrict__ W,
                             __nv_bfloat16* __restrict__ hi,
                             __nv_bfloat16* __restrict__ lo,
                             int Krows, int Ncols) {
    __shared__ float tile[32][33];
    int n0 = blockIdx.x * 32, k0 = blockIdx.y * 32;
    int tx = threadIdx.x, ty = threadIdx.y;
#pragma unroll
    for (int i = 0; i < 4; i++)
        tile[ty + 8 * i][tx] = W[(size_t)(k0 + ty + 8 * i) * Ncols + n0 + tx];
    __syncthreads();
#pragma unroll
    for (int i = 0; i < 4; i++) {
        int r = ty + 8 * i;
        float v = tile[tx][r];
        size_t o = (size_t)(n0 + r) * Krows + k0 + tx;
        __nv_bfloat16 h = __float2bfloat16(v);
        hi[o] = h;
        lo[o] = __float2bfloat16(v - __bfloat162float(h));
    }
}

// ---------------- LayerNorm -> bf16 hi/lo ----------------
__global__ void ln_kernel(const float* __restrict__ x,
                          const float* __restrict__ gamma,
                          const float* __restrict__ beta,
                          __nv_bfloat16* __restrict__ ohi,
                          __nv_bfloat16* __restrict__ olo) {
    int row = blockIdx.x;
    const float4* xr = (const float4*)(x + (size_t)row * DM_);
    float4 v[4];
    float sum = 0.f, sq = 0.f;
#pragma unroll
    for (int i = 0; i < 4; i++) {
        v[i] = xr[threadIdx.x + 256 * i];
        sum += v[i].x + v[i].y + v[i].z + v[i].w;
        sq  += v[i].x * v[i].x + v[i].y * v[i].y + v[i].z * v[i].z + v[i].w * v[i].w;
    }
#pragma unroll
    for (int o = 16; o; o >>= 1) {
        sum += __shfl_xor_sync(0xffffffffu, sum, o);
        sq  += __shfl_xor_sync(0xffffffffu, sq,  o);
    }
    __shared__ float ssum[8], ssq[8];
    int warp = threadIdx.x >> 5, lane = threadIdx.x & 31;
    if (lane == 0) { ssum[warp] = sum; ssq[warp] = sq; }
    __syncthreads();
    sum = 0.f; sq = 0.f;
#pragma unroll
    for (int i = 0; i < 8; i++) { sum += ssum[i]; sq += ssq[i]; }
    float mu  = sum * (1.0f / DM_);
    float var = sq * (1.0f / DM_) - mu * mu;
    float inv = rsqrtf(var + 1e-5f);
    const float4* g4 = (const float4*)gamma;
    const float4* b4 = (const float4*)beta;
#pragma unroll
    for (int i = 0; i < 4; i++) {
        int idx = threadIdx.x + 256 * i;
        float4 g = g4[idx], b = b4[idx];
        size_t base = (size_t)row * DM_ + idx * 4;
        split_store((v[i].x - mu) * inv * g.x + b.x, ohi + base + 0, olo + base + 0);
        split_store((v[i].y - mu) * inv * g.y + b.y, ohi + base + 1, olo + base + 1);
        split_store((v[i].z - mu) * inv * g.z + b.z, ohi + base + 2, olo + base + 2);
        split_store((v[i].w - mu) * inv * g.w + b.w, ohi + base + 3, olo + base + 3);
    }
}

// ---------------- RoPE (GPT-J interleaved) ----------------
__global__ void rope_kernel(float* __restrict__ qkv, const int* __restrict__ positions) {
    int idx = blockIdx.x * blockDim.x + threadIdx.x;
    int i     = idx & 31;
    int which = (idx >> 5) & 1;
    int h     = (idx >> 6) & 15;
    int t     = idx >> 10;
    float inv = (float)pow(10000.0, -(double)i / 32.0);
    float ang = (float)positions[t] * inv;
    float s, c;
    sincosf(ang, &s, &c);
    float* p = qkv + (size_t)t * (3 * DM_) + (size_t)which * DM_ + h * HD_ + 2 * i;
    float x1 = p[0], x2 = p[1];
    p[0] = x1 * c - x2 * s;
    p[1] = x2 * c + x1 * s;
}

// ---------------- q/k split to [H][T][HD] bf16 hi/lo ----------------
__global__ void qksplit_kernel(const float* __restrict__ qkv,
                               __nv_bfloat16* __restrict__ qh, __nv_bfloat16* __restrict__ ql,
                               __nv_bfloat16* __restrict__ kh, __nv_bfloat16* __restrict__ kl) {
    int idx = blockIdx.x * 256 + threadIdx.x;          // 0 .. 2*T*DM/4
    const int per = T_ * DM_ / 4;
    int half = idx >= per;
    int rem = idx - half * per;
    int t = rem / (DM_ / 4);
    int e4 = rem - t * (DM_ / 4);
    float4 v = *(const float4*)(qkv + (size_t)t * (3 * DM_) + half * DM_ + e4 * 4);
    int hh = (e4 * 4) >> 8;
    int hd = (e4 * 4) & 255;
    size_t dst = ((size_t)(hh * T_ + t)) * 256 + hd;
    __nv_bfloat16 *oh = half ? kh : qh, *ol = half ? kl : ql;
    split_store(v.x, oh + dst + 0, ol + dst + 0);
    split_store(v.y, oh + dst + 1, ol + dst + 1);
    split_store(v.z, oh + dst + 2, ol + dst + 2);
    split_store(v.w, oh + dst + 3, ol + dst + 3);
}

// ---------------- v split + transpose to [H][HD][T] bf16 hi/lo --------
__global__ void vsplitT_kernel(const float* __restrict__ qkv,
                               __nv_bfloat16* __restrict__ vth, __nv_bfloat16* __restrict__ vtl) {
    __shared__ float tile[32][33];
    int t0 = blockIdx.x * 32, hd0 = blockIdx.y * 32, h = blockIdx.z;
    int tx = threadIdx.x, ty = threadIdx.y;
#pragma unroll
    for (int i = 0; i < 4; i++)
        tile[ty + 8 * i][tx] = qkv[(size_t)(t0 + ty + 8 * i) * (3 * DM_) + 2 * DM_ + h * 256 + hd0 + tx];
    __syncthreads();
#pragma unroll
    for (int i = 0; i < 4; i++) {
        int r = ty + 8 * i;                 // hd within tile
        float v = tile[tx][r];              // = V[t0+tx][hd0+r]
        size_t o = ((size_t)(h * 256 + hd0 + r)) * T_ + t0 + tx;
        split_store(v, vth + o, vtl + o);
    }
}

__device__ __forceinline__ float gelu_tanh(float x) {
    float x3 = x * x * x;
    float t  = tanhf(0.7978845608028654f * (x + 0.044715f * x3));
    return 0.5f * x * (1.0f + t);
}

// ---------------- final merge: out += attnout ----------------
__global__ void add_kernel(float* __restrict__ out, const float* __restrict__ a) {
    int i = blockIdx.x * blockDim.x + threadIdx.x;
    float4 o = ((const float4*)out)[i];
    float4 v = ((const float4*)a)[i];
    o.x += v.x; o.y += v.y; o.z += v.z; o.w += v.w;
    ((float4*)out)[i] = o;
}

// ---------------- mma.sync split-bf16 GEMM (unchanged from R10) -------
#define KC 32
#define ARR_BYTES 8192
#define AHI_OFF 0
#define ALO_OFF 8192
#define BHI_OFF 16384
#define BLO_OFF 24576
#define STAGE_BYTES 32768
#define NSTAGE 3
#define GEMM_SMEM (NSTAGE * STAGE_BYTES)

template <int EPI>
__global__ void __launch_bounds__(256, 2)
mma_gemm(const __nv_bfloat16* __restrict__ Ahi, const __nv_bfloat16* __restrict__ Alo,
         const __nv_bfloat16* __restrict__ Bhi, const __nv_bfloat16* __restrict__ Blo,
         float* __restrict__ C,
         __nv_bfloat16* __restrict__ Ohi, __nv_bfloat16* __restrict__ Olo,
         const float* __restrict__ bias, const float* __restrict__ res,
         int M, int N, int K) {
    extern __shared__ char smem[];
    const uint32_t sb0 = smem_u32(smem);
    int tid = threadIdx.x;
    int lane = tid & 31, wid = tid >> 5;
    int wm = wid >> 2, wn = wid & 3;

    int nbn = N / 128, nbm = M / 128;
    const int SWT = 8;
    int per = SWT * nbm;
    int ggrp = blockIdx.x / per, rem = blockIdx.x - ggrp * per;
    int bn0 = ggrp * SWT;
    int w = nbn - bn0; if (w > SWT) w = SWT;
    int bn = bn0 + rem % w;
    int bm = rem / w;

    float acc[4][4][4];
#pragma unroll
    for (int i = 0; i < 4; i++)
#pragma unroll
        for (int j = 0; j < 4; j++)
#pragma unroll
            for (int q = 0; q < 4; q++) acc[i][j][q] = 0.f;

    auto load_stage = [&](int s, int k0) {
        uint32_t sb = sb0 + s * STAGE_BYTES;
#pragma unroll
        for (int j = 0; j < 2; j++) {
            int id  = tid + 256 * j;
            int row = id >> 2, c = id & 3;
            uint32_t d = row * 64 + ((c ^ ((row >> 1) & 3)) << 4);
            size_t goA = (size_t)(bm * 128 + row) * K + k0 + c * 8;
            size_t goB = (size_t)(bn * 128 + row) * K + k0 + c * 8;
            cp_async16(sb + AHI_OFF + d, Ahi + goA);
            cp_async16(sb + ALO_OFF + d, Alo + goA);
            cp_async16(sb + BHI_OFF + d, Bhi + goB);
            cp_async16(sb + BLO_OFF + d, Blo + goB);
        }
    };

    load_stage(0, 0); CP_COMMIT();
    load_stage(1, KC); CP_COMMIT();

    int hi4 = lane >> 4;
    int rA[4], swA[4], rB0, rB1, swB0, swB1;
#pragma unroll
    for (int i = 0; i < 4; i++) {
        int r = wm * 64 + i * 16 + (lane & 15);
        rA[i] = r * 64;
        swA[i] = (r >> 1) & 3;
    }
    {
        int r0 = wn * 32 + (lane & 15);
        int r1 = r0 + 16;
        rB0 = r0 * 64; swB0 = (r0 >> 1) & 3;
        rB1 = r1 * 64; swB1 = (r1 >> 1) & 3;
    }

    int nk = K / KC;
    int st = 0, ld = 2;
    for (int kc = 0; kc < nk; kc++) {
        CP_WAIT1();
        __syncthreads();
        if (kc + 2 < nk) load_stage(ld, (kc + 2) * KC);
        CP_COMMIT();
        uint32_t base = sb0 + st * STAGE_BYTES;
#pragma unroll
        for (int ks = 0; ks < 2; ks++) {
            int c = ks * 2 + hi4;
            uint32_t bh[8], bl[8];
            ldsm4(bh,     base + BHI_OFF + rB0 + ((c ^ swB0) << 4));
            ldsm4(bh + 4, base + BHI_OFF + rB1 + ((c ^ swB1) << 4));
            ldsm4(bl,     base + BLO_OFF + rB0 + ((c ^ swB0) << 4));
            ldsm4(bl + 4, base + BLO_OFF + rB1 + ((c ^ swB1) << 4));
#pragma unroll
            for (int i = 0; i < 4; i++) {
                uint32_t ah[4], al[4];
                ldsm4(ah, base + AHI_OFF + rA[i] + ((c ^ swA[i]) << 4));
                ldsm4(al, base + ALO_OFF + rA[i] + ((c ^ swA[i]) << 4));
#pragma unroll
                for (int j = 0; j < 4; j++) {
                    int j2 = j >> 1, ss = j & 1;
                    uint32_t b0h = bh[j2 * 4 + ss], b1h = bh[j2 * 4 + ss + 2];
                    uint32_t b0l = bl[j2 * 4 + ss], b1l = bl[j2 * 4 + ss + 2];
                    mma16816(acc[i][j], ah, b0h, b1h);
                    mma16816(acc[i][j], ah, b0l, b1l);
                    mma16816(acc[i][j], al, b0h, b1h);
                }
            }
        }
        st = (st == 2) ? 0 : st + 1;
        ld = (ld == 2) ? 0 : ld + 1;
    }

    int gq = lane >> 2, cc = lane & 3;
#pragma unroll
    for (int i = 0; i < 4; i++) {
#pragma unroll
        for (int j = 0; j < 4; j++) {
            int row = bm * 128 + wm * 64 + i * 16 + gq;
            int col = bn * 128 + wn * 32 + j * 8 + 2 * cc;
            float* a4 = acc[i][j];
#pragma unroll
            for (int half = 0; half < 2; half++) {
                int r = row + 8 * half;
                float v0 = a4[2 * half], v1 = a4[2 * half + 1];
                size_t base = (size_t)r * N + col;
                if (EPI == 0) {
                    *(float2*)(C + base) = make_float2(v0, v1);
                } else if (EPI == 1) {
                    float g0 = gelu_tanh(v0 + bias[col]);
                    float g1 = gelu_tanh(v1 + bias[col + 1]);
                    split_store(g0, Ohi + base, Olo + base);
                    split_store(g1, Ohi + base + 1, Olo + base + 1);
                } else if (EPI == 2) {
                    float2 rr = *(const float2*)(res + base);
                    *(float2*)(C + base) = make_float2(v0 + bias[col] + rr.x,
                                                       v1 + bias[col + 1] + rr.y);
                } else {
                    float2 cur = *(float2*)(C + base);
                    *(float2*)(C + base) = make_float2(cur.x + v0, cur.y + v1);
                }
            }
        }
    }
}

// ---------------- tensor-core causal flash attention ----------------
// CTA: 64 q rows x one head, 128 threads (4 warps x 16 rows).
// Q resident in smem (hi/lo, 512B rows); K/V tiles (BK=32) double-buffered.
// S = QK^T via 3-pass split-bf16; online softmax fp32; ctx += P V via
// 3-pass split (P hi/lo computed in-register, V pre-transposed [H][HD][T]).
#define BQ2 64
#define BK2 32
#define SMQ_HI 0
#define SMQ_LO 32768
#define SMSTG0 65536
#define SMSTG  65536
#define SMK_HI 0
#define SMK_LO 16384
#define SMV_HI 32768
#define SMV_LO 49152
#define ATT_SMEM 196608

__global__ void __launch_bounds__(128, 1)
attn_mma(const __nv_bfloat16* __restrict__ qh, const __nv_bfloat16* __restrict__ ql,
         const __nv_bfloat16* __restrict__ kh, const __nv_bfloat16* __restrict__ kl,
         const __nv_bfloat16* __restrict__ vth, const __nv_bfloat16* __restrict__ vtl,
         __nv_bfloat16* __restrict__ chi, __nv_bfloat16* __restrict__ clo) {
    extern __shared__ char smem[];
    uint32_t sb = smem_u32(smem);
    int h = blockIdx.y;
    int qb = (gridDim.x - 1) - blockIdx.x;      // big tiles first
    int tid = threadIdx.x, lane = tid & 31, w = tid >> 5;

    auto load_q = [&]() {
#pragma unroll
        for (int j = 0; j < 16; j++) {
            int id = tid + 128 * j;             // 0..2047
            int row = id >> 5, c = id & 31;
            uint32_t d = row * 512 + ((c ^ ((row & 7) << 2)) << 4);
            size_t src = ((size_t)(h * T_ + qb * BQ2 + row)) * 256 + c * 8;
            cp_async16(sb + SMQ_HI + d, qh + src);
            cp_async16(sb + SMQ_LO + d, ql + src);
        }
    };
    auto load_kv = [&](int s, int kt) {
        uint32_t st = sb + SMSTG0 + s * SMSTG;
#pragma unroll
        for (int j = 0; j < 8; j++) {
            int id = tid + 128 * j;             // 0..1023
            int row = id >> 5, c = id & 31;
            uint32_t d = row * 512 + ((c ^ ((row & 7) << 2)) << 4);
            size_t src = ((size_t)(h * T_ + kt * BK2 + row)) * 256 + c * 8;
            cp_async16(st + SMK_HI + d, kh + src);
            cp_async16(st + SMK_LO + d, kl + src);
            int vrow = id >> 2, vc = id & 3;
            uint32_t vd = vrow * 64 + ((vc ^ ((vrow >> 1) & 3)) << 4);
            size_t vs = ((size_t)(h * 256 + vrow)) * T_ + kt * BK2 + vc * 8;
            cp_async16(st + SMV_HI + vd, vth + vs);
            cp_async16(st + SMV_LO + vd, vtl + vs);
        }
    };

    float ctx[32][4];
#pragma unroll
    for (int i = 0; i < 32; i++)
#pragma unroll
        for (int q = 0; q < 4; q++) ctx[i][q] = 0.f;
    float m0 = -CUDART_INF_F, m1 = -CUDART_INF_F, l0 = 0.f, l1 = 0.f;

    int ntiles = 2 * qb + 2;
    load_q(); load_kv(0, 0); CP_COMMIT();
    int s = 0;
    for (int kt = 0; kt < ntiles; kt++) {
        CP_WAIT0();
        __syncthreads();
        if (kt + 1 < ntiles) { load_kv(s ^ 1, kt + 1); CP_COMMIT(); }
        uint32_t stg = sb + SMSTG0 + s * SMSTG;

        // ---- S = Q K^T (3-pass split) ----
        float sacc[4][4];
#pragma unroll
        for (int nb = 0; nb < 4; nb++)
#pragma unroll
            for (int q = 0; q < 4; q++) sacc[nb][q] = 0.f;
#pragma unroll 4
        for (int ks = 0; ks < 16; ks++) {
            int arow = w * 16 + (lane & 15);
            int ac = ks * 2 + (lane >> 4);
            uint32_t aoff = arow * 512 + ((ac ^ ((arow & 7) << 2)) << 4);
            uint32_t qhf[4], qlf[4];
            ldsm4(qhf, sb + SMQ_HI + aoff);
            ldsm4(qlf, sb + SMQ_LO + aoff);
            uint32_t kbh[8], kbl[8];
#pragma unroll
            for (int p2 = 0; p2 < 2; p2++) {
                int krow = p2 * 16 + (lane & 15);
                uint32_t koff = krow * 512 + ((ac ^ ((krow & 7) << 2)) << 4);
                ldsm4(kbh + 4 * p2, stg + SMK_HI + koff);
                ldsm4(kbl + 4 * p2, stg + SMK_LO + koff);
            }
#pragma unroll
            for (int nb = 0; nb < 4; nb++) {
                int p2 = nb >> 1, ss = nb & 1;
                mma16816(sacc[nb], qhf, kbh[p2 * 4 + ss], kbh[p2 * 4 + ss + 2]);
            }
#pragma unroll
            for (int nb = 0; nb < 4; nb++) {
                int p2 = nb >> 1, ss = nb & 1;
                mma16816(sacc[nb], qhf, kbl[p2 * 4 + ss], kbl[p2 * 4 + ss + 2]);
            }
#pragma unroll
            for (int nb = 0; nb < 4; nb++) {
                int p2 = nb >> 1, ss = nb & 1;
                mma16816(sacc[nb], qlf, kbh[p2 * 4 + ss], kbh[p2 * 4 + ss + 2]);
            }
        }

        // ---- mask + online softmax ----
        int r0 = qb * BQ2 + w * 16 + (lane >> 2);
        int r1 = r0 + 8;
        float mloc0 = -CUDART_INF_F, mloc1 = -CUDART_INF_F;
#pragma unroll
        for (int nb = 0; nb < 4; nb++) {
            int colb = kt * BK2 + nb * 8 + (lane & 3) * 2;
#pragma unroll
            for (int e = 0; e < 2; e++) {
                float v0 = sacc[nb][e] * 0.0625f;
                float v1 = sacc[nb][2 + e] * 0.0625f;
                if (colb + e > r0) v0 = -CUDART_INF_F;
                if (colb + e > r1) v1 = -CUDART_INF_F;
                sacc[nb][e] = v0; sacc[nb][2 + e] = v1;
                mloc0 = fmaxf(mloc0, v0); mloc1 = fmaxf(mloc1, v1);
            }
        }
        mloc0 = fmaxf(mloc0, __shfl_xor_sync(0xffffffffu, mloc0, 1));
        mloc0 = fmaxf(mloc0, __shfl_xor_sync(0xffffffffu, mloc0, 2));
        mloc1 = fmaxf(mloc1, __shfl_xor_sync(0xffffffffu, mloc1, 1));
        mloc1 = fmaxf(mloc1, __shfl_xor_sync(0xffffffffu, mloc1, 2));
        float mn0 = fmaxf(m0, mloc0), mn1 = fmaxf(m1, mloc1);
        float al0 = __expf(m0 - mn0), al1 = __expf(m1 - mn1);
        float ls0 = 0.f, ls1 = 0.f;
#pragma unroll
        for (int nb = 0; nb < 4; nb++) {
#pragma unroll
            for (int e = 0; e < 2; e++) {
                float p0 = __expf(sacc[nb][e] - mn0);
                float p1 = __expf(sacc[nb][2 + e] - mn1);
                ls0 += p0; ls1 += p1;
                sacc[nb][e] = p0; sacc[nb][2 + e] = p1;
            }
        }
        ls0 += __shfl_xor_sync(0xffffffffu, ls0, 1);
        ls0 += __shfl_xor_sync(0xffffffffu, ls0, 2);
        ls1 += __shfl_xor_sync(0xffffffffu, ls1, 1);
        ls1 += __shfl_xor_sync(0xffffffffu, ls1, 2);
        l0 = l0 * al0 + ls0;
        l1 = l1 * al1 + ls1;
        m0 = mn0; m1 = mn1;
#pragma unroll
        for (int nv = 0; nv < 32; nv++) {
            ctx[nv][0] *= al0; ctx[nv][1] *= al0;
            ctx[nv][2] *= al1; ctx[nv][3] *= al1;
        }

        // ---- P fragments (hi/lo) ----
        uint32_t pah[2][4], pal[2][4];
#pragma unroll
        for (int ksp = 0; ksp < 2; ksp++) {
#pragma unroll
            for (int half = 0; half < 2; half++) {
                int nb = ksp * 2 + half;
                float p00 = sacc[nb][0], p01 = sacc[nb][1];
                float p10 = sacc[nb][2], p11 = sacc[nb][3];
                float h00 = __bfloat162float(__float2bfloat16(p00));
                float h01 = __bfloat162float(__float2bfloat16(p01));
                float h10 = __bfloat162float(__float2bfloat16(p10));
                float h11 = __bfloat162float(__float2bfloat16(p11));
                pah[ksp][half * 2 + 0] = pack_bf16x2(h00, h01);
                pah[ksp][half * 2 + 1] = pack_bf16x2(h10, h11);
                pal[ksp][half * 2 + 0] = pack_bf16x2(p00 - h00, p01 - h01);
                pal[ksp][half * 2 + 1] = pack_bf16x2(p10 - h10, p11 - h11);
            }
        }

        // ---- ctx += P V (3-pass split) ----
#pragma unroll
        for (int ksv = 0; ksv < 2; ksv++) {
#pragma unroll
            for (int np = 0; np < 16; np += 2) {
                uint32_t vbh[8], vbl[8];
#pragma unroll
                for (int q2 = 0; q2 < 2; q2++) {
                    int vrow = (np + q2) * 16 + (lane & 15);
                    int vc = ksv * 2 + (lane >> 4);
                    uint32_t voff = vrow * 64 + ((vc ^ ((vrow >> 1) & 3)) << 4);
                    ldsm4(vbh + 4 * q2, stg + SMV_HI + voff);
                    ldsm4(vbl + 4 * q2, stg + SMV_LO + voff);
                }
#pragma unroll
                for (int q2 = 0; q2 < 2; q2++)
#pragma unroll
                    for (int ss = 0; ss < 2; ss++) {
                        int nv = (np + q2) * 2 + ss;
                        mma16816(ctx[nv], pah[ksv], vbh[q2 * 4 + ss], vbh[q2 * 4 + ss + 2]);
                    }
#pragma unroll
                for (int q2 = 0; q2 < 2; q2++)
#pragma unroll
                    for (int ss = 0; ss < 2; ss++) {
                        int nv = (np + q2) * 2 + ss;
                        mma16816(ctx[nv], pah[ksv], vbl[q2 * 4 + ss], vbl[q2 * 4 + ss + 2]);
                    }
#pragma unroll
                for (int q2 = 0; q2 < 2; q2++)
#pragma unroll
                    for (int ss = 0; ss < 2; ss++) {
                        int nv = (np + q2) * 2 + ss;
                        mma16816(ctx[nv], pal[ksv], vbh[q2 * 4 + ss], vbh[q2 * 4 + ss + 2]);
                    }
            }
        }
        s ^= 1;
    }

    // ---- epilogue: normalize, split-store ctx ----
    float inv0 = 1.f / l0, inv1 = 1.f / l1;
    int tr0 = qb * BQ2 + w * 16 + (lane >> 2), tr1 = tr0 + 8;
#pragma unroll
    for (int nv = 0; nv < 32; nv++) {
        int col = h * 256 + nv * 8 + (lane & 3) * 2;
        size_t o0 = (size_t)tr0 * DM_ + col;
        size_t o1 = (size_t)tr1 * DM_ + col;
        split_store(ctx[nv][0] * inv0, chi + o0,     clo + o0);
        split_store(ctx[nv][1] * inv0, chi + o0 + 1, clo + o0 + 1);
        split_store(ctx[nv][2] * inv1, chi + o1,     clo + o1);
        split_store(ctx[nv][3] * inv1, chi + o1 + 1, clo + o1 + 1);
    }
}

// ---------------- launch ----------------
extern "C" void kernel_launch(void* const* d_in, const int* in_sizes, int n_in,
                              void* d_out, int out_size) {
    const int*   positions = (const int*)  d_in[0];
    const float* hidden    = (const float*)d_in[1];
    const float* ln_g      = (const float*)d_in[2];
    const float* ln_b      = (const float*)d_in[3];
    const float* w_qkv     = (const float*)d_in[4];
    const float* w_out     = (const float*)d_in[5];
    const float* w_fc_in   = (const float*)d_in[6];
    const float* b_fc_in   = (const float*)d_in[7];
    const float* w_fc_out  = (const float*)d_in[8];
    const float* b_fc_out  = (const float*)d_in[9];
    float* out = (float*)d_out;

    __nv_bfloat16 *wqh, *wql, *woh, *wol, *wih, *wil, *wfh, *wfl;
    __nv_bfloat16 *lnh, *lnl, *ach, *acl, *cxh, *cxl;
    __nv_bfloat16 *pqh, *pql, *pkh, *pkl, *pvh, *pvl;
    float *p_qkv, *p_att;
    cudaGetSymbolAddress((void**)&wqh, g_wqkvT_hi);  cudaGetSymbolAddress((void**)&wql, g_wqkvT_lo);
    cudaGetSymbolAddress((void**)&woh, g_woutT_hi);  cudaGetSymbolAddress((void**)&wol, g_woutT_lo);
    cudaGetSymbolAddress((void**)&wih, g_wfciT_hi);  cudaGetSymbolAddress((void**)&wil, g_wfciT_lo);
    cudaGetSymbolAddress((void**)&wfh, g_wfcoT_hi);  cudaGetSymbolAddress((void**)&wfl, g_wfcoT_lo);
    cudaGetSymbolAddress((void**)&lnh, g_ln_hi);     cudaGetSymbolAddress((void**)&lnl, g_ln_lo);
    cudaGetSymbolAddress((void**)&ach, g_act_hi);    cudaGetSymbolAddress((void**)&acl, g_act_lo);
    cudaGetSymbolAddress((void**)&cxh, g_ctx_hi);    cudaGetSymbolAddress((void**)&cxl, g_ctx_lo);
    cudaGetSymbolAddress((void**)&pqh, g_qh);        cudaGetSymbolAddress((void**)&pql, g_ql);
    cudaGetSymbolAddress((void**)&pkh, g_kh);        cudaGetSymbolAddress((void**)&pkl, g_kl);
    cudaGetSymbolAddress((void**)&pvh, g_vth);       cudaGetSymbolAddress((void**)&pvl, g_vtl);
    cudaGetSymbolAddress((void**)&p_qkv, g_qkv);
    cudaGetSymbolAddress((void**)&p_att, g_attnout);

    cudaFuncSetAttribute(mma_gemm<0>, cudaFuncAttributeMaxDynamicSharedMemorySize, GEMM_SMEM);
    cudaFuncSetAttribute(mma_gemm<1>, cudaFuncAttributeMaxDynamicSharedMemorySize, GEMM_SMEM);
    cudaFuncSetAttribute(mma_gemm<2>, cudaFuncAttributeMaxDynamicSharedMemorySize, GEMM_SMEM);
    cudaFuncSetAttribute(attn_mma,    cudaFuncAttributeMaxDynamicSharedMemorySize, ATT_SMEM);

    static cudaStream_t s1 = nullptr, s2 = nullptr;
    static cudaEvent_t evFork = nullptr, evLN = nullptr, evJoin1 = nullptr, evJoin2 = nullptr;
    if (!s1) {
        cudaStreamCreateWithFlags(&s1, cudaStreamNonBlocking);
        cudaStreamCreateWithFlags(&s2, cudaStreamNonBlocking);
        cudaEventCreateWithFlags(&evFork,  cudaEventDisableTiming);
        cudaEventCreateWithFlags(&evLN,    cudaEventDisableTiming);
        cudaEventCreateWithFlags(&evJoin1, cudaEventDisableTiming);
        cudaEventCreateWithFlags(&evJoin2, cudaEventDisableTiming);
    }

    dim3 cb(32, 8);

    cudaEventRecord(evFork, 0);
    cudaStreamWaitEvent(s1, evFork, 0);
    cudaStreamWaitEvent(s2, evFork, 0);

    // ---- chain A prep (s1): attention-path weights + LN ----
    convT_kernel<<<dim3(3 * DM_ / 32, DM_ / 32), cb, 0, s1>>>(w_qkv, wqh, wql, DM_, 3 * DM_);
    convT_kernel<<<dim3(DM_ / 32,     DM_ / 32), cb, 0, s1>>>(w_out, woh, wol, DM_, DM_);
    ln_kernel<<<T_, 256, 0, s1>>>(hidden, ln_g, ln_b, lnh, lnl);
    cudaEventRecord(evLN, s1);

    // ---- chain B (s2): MLP weights, then fc_in -> fc_out ----
    convT_kernel<<<dim3(DFF_ / 32, DM_ / 32), cb, 0, s2>>>(w_fc_in,  wih, wil, DM_,  DFF_);
    convT_kernel<<<dim3(DM_ / 32, DFF_ / 32), cb, 0, s2>>>(w_fc_out, wfh, wfl, DFF_, DM_);
    cudaStreamWaitEvent(s2, evLN, 0);
    mma_gemm<1><<<(T_ / 128) * (DFF_ / 128), 256, GEMM_SMEM, s2>>>(
        lnh, lnl, wih, wil, nullptr, ach, acl, b_fc_in, nullptr, T_, DFF_, DM_);
    mma_gemm<2><<<(T_ / 128) * (DM_ / 128), 256, GEMM_SMEM, s2>>>(
        ach, acl, wfh, wfl, out, nullptr, nullptr, b_fc_out, hidden, T_, DM_, DFF_);
    cudaEventRecord(evJoin2, s2);

    // ---- chain A (s1): QKV -> RoPE -> split -> attention -> out-proj ----
    mma_gemm<0><<<(T_ / 128) * (3 * DM_ / 128), 256, GEMM_SMEM, s1>>>(
        lnh, lnl, wqh, wql, p_qkv, nullptr, nullptr, nullptr, nullptr, T_, 3 * DM_, DM_);
    rope_kernel<<<(T_ * H_ * 64) / 256, 256, 0, s1>>>(p_qkv, positions);
    qksplit_kernel<<<(2 * T_ * DM_ / 4) / 256, 256, 0, s1>>>(p_qkv, pqh, pql, pkh, pkl);
    vsplitT_kernel<<<dim3(T_ / 32, HD_ / 32, H_), cb, 0, s1>>>(p_qkv, pvh, pvl);
    attn_mma<<<dim3(T_ / BQ2, H_), 128, ATT_SMEM, s1>>>(pqh, pql, pkh, pkl, pvh, pvl, cxh, cxl);
    mma_gemm<0><<<(T_ / 128) * (DM_ / 128), 256, GEMM_SMEM, s1>>>(
        cxh, cxl, woh, wol, p_att, nullptr, nullptr, nullptr, nullptr, T_, DM_, DM_);
    cudaEventRecord(evJoin1, s1);

    // ---- join, final merge ----
    cudaStreamWaitEvent(0, evJoin1, 0);
    cudaStreamWaitEvent(0, evJoin2, 0);
    add_kernel<<<(T_ * DM_ / 4) / 256, 256>>>(out, p_att);
}